// round 5
// baseline (speedup 1.0000x reference)
#include <cuda_runtime.h>
#include <cuda_bf16.h>
#include <math.h>

// ---------------- problem constants ----------------
#define TT   100      // time steps after conv
#define BB   512      // batch
#define WW   18       // conv output width
#define CC   32       // conv channels
#define FF   576      // WW*CC lstm input features
#define HH   128      // hidden
#define GG   512      // 4*HH gates
#define NC   12       // classes

// ---------------- device scratch ----------------
__device__ float g_seq [TT * BB * FF];
__device__ float g_xp  [TT * BB * GG];
__device__ float g_h1  [TT * BB * HH];
__device__ float g_h2  [TT * BB * HH];
__device__ float g_wattT[HH * HH];
__device__ float g_attn [TT * BB];
__device__ float g_pooled[BB * HH];

__device__ __forceinline__ float sigf(float x) { return 1.0f / (1.0f + expf(-x)); }

// =====================================================================
// Conv: one block per batch image. Whole image in smem (812*40*4=127KB).
// =====================================================================
__global__ void __launch_bounds__(256, 1) conv_kernel(const float* __restrict__ x,
                                                      const float* __restrict__ cw,
                                                      const float* __restrict__ cb) {
    extern __shared__ float s_img[];   // [812][40]
    int b = blockIdx.x;
    int tid = threadIdx.x;
    int wid = tid >> 5, lane = tid & 31;
    int c = lane;

    const float4* src = (const float4*)(x + (size_t)b * 812 * 40);
    float4* dst = (float4*)s_img;
    for (int i = tid; i < 812 * 10; i += 256) dst[i] = src[i];

    float wr[100];
#pragma unroll
    for (int i = 0; i < 100; i++) wr[i] = __ldg(&cw[c * 100 + i]);
    float bv = __ldg(&cb[c]);
    __syncthreads();

    for (int p = wid; p < 50; p += 8) {          // t0 = 2p, t1 = 2p+1
        int base_row = 16 * p;
        float acc[2][18];
#pragma unroll
        for (int w = 0; w < 18; w++) { acc[0][w] = bv; acc[1][w] = bv; }

#pragma unroll
        for (int rr = 0; rr < 28; rr++) {
            const float* prow = &s_img[(base_row + rr) * 40];
#pragma unroll
            for (int j = 0; j < 40; j++) {
                float pv = prow[j];
#pragma unroll
                for (int kw = 0; kw < 5; kw++) {
                    int d = j - kw;
                    if (d >= 0 && (d & 1) == 0) {
                        int w = d >> 1;
                        if (w < 18) {
                            if (rr < 20) acc[0][w] += wr[rr * 5 + kw] * pv;
                            if (rr >= 8) acc[1][w] += wr[(rr - 8) * 5 + kw] * pv;
                        }
                    }
                }
            }
        }
#pragma unroll
        for (int ts = 0; ts < 2; ts++) {
            int t = 2 * p + ts;
            float* out = &g_seq[((size_t)t * BB + b) * FF];
#pragma unroll
            for (int w = 0; w < 18; w++)
                out[w * 32 + c] = fmaxf(acc[ts][w], 0.0f);
        }
    }
}

// ---------------- generic transpose (used for W_att only) ----------------
__global__ void transpose_kernel(const float* __restrict__ in, float* __restrict__ out,
                                 int rows, int cols) {
    int idx = blockIdx.x * 256 + threadIdx.x;
    if (idx < rows * cols) {
        int r = idx / cols, c = idx % cols;
        out[c * rows + r] = in[idx];
    }
}

// =====================================================================
// fp32 SGEMM: C[M,N] = A[M,K] @ B[N,K]^T + bias0 + bias1
// 128x128 tile, BK=16, 8x8 micro-tile, double-buffered smem.
// =====================================================================
__global__ void __launch_bounds__(256) gemm128(const float* __restrict__ A,
                                               const float* __restrict__ Bm,
                                               const float* __restrict__ bias0,
                                               const float* __restrict__ bias1,
                                               float* __restrict__ C,
                                               int M, int N, int K) {
    __shared__ float As[2][16][128];
    __shared__ float Bs[2][16][128];
    int tid = threadIdx.x;
    int tx = tid & 15, ty = tid >> 4;
    int bm = blockIdx.y * 128, bn = blockIdx.x * 128;

    int r0 = tid >> 2, kq = (tid & 3) << 2;
    int r1 = r0 + 64;
    const float* Ap0 = A + (size_t)(bm + r0) * K + kq;
    const float* Ap1 = A + (size_t)(bm + r1) * K + kq;
    const float* Bp0 = Bm + (size_t)(bn + r0) * K + kq;
    const float* Bp1 = Bm + (size_t)(bn + r1) * K + kq;

    float4 a0 = *(const float4*)Ap0;
    float4 a1 = *(const float4*)Ap1;
    float4 b0 = *(const float4*)Bp0;
    float4 b1 = *(const float4*)Bp1;

    As[0][kq + 0][r0] = a0.x; As[0][kq + 1][r0] = a0.y; As[0][kq + 2][r0] = a0.z; As[0][kq + 3][r0] = a0.w;
    As[0][kq + 0][r1] = a1.x; As[0][kq + 1][r1] = a1.y; As[0][kq + 2][r1] = a1.z; As[0][kq + 3][r1] = a1.w;
    Bs[0][kq + 0][r0] = b0.x; Bs[0][kq + 1][r0] = b0.y; Bs[0][kq + 2][r0] = b0.z; Bs[0][kq + 3][r0] = b0.w;
    Bs[0][kq + 0][r1] = b1.x; Bs[0][kq + 1][r1] = b1.y; Bs[0][kq + 2][r1] = b1.z; Bs[0][kq + 3][r1] = b1.w;
    __syncthreads();

    float acc[8][8];
#pragma unroll
    for (int i = 0; i < 8; i++)
#pragma unroll
        for (int j = 0; j < 8; j++) acc[i][j] = 0.0f;

    int buf = 0;
    for (int kt = 0; kt < K; kt += 16) {
        bool more = (kt + 16) < K;
        if (more) {
            a0 = *(const float4*)(Ap0 + kt + 16);
            a1 = *(const float4*)(Ap1 + kt + 16);
            b0 = *(const float4*)(Bp0 + kt + 16);
            b1 = *(const float4*)(Bp1 + kt + 16);
        }

#pragma unroll
        for (int kk = 0; kk < 16; kk++) {
            float4 x0 = *(const float4*)&As[buf][kk][ty * 8];
            float4 x1 = *(const float4*)&As[buf][kk][ty * 8 + 4];
            float4 y0 = *(const float4*)&Bs[buf][kk][tx * 8];
            float4 y1 = *(const float4*)&Bs[buf][kk][tx * 8 + 4];
            float xa[8] = {x0.x, x0.y, x0.z, x0.w, x1.x, x1.y, x1.z, x1.w};
            float yb[8] = {y0.x, y0.y, y0.z, y0.w, y1.x, y1.y, y1.z, y1.w};
#pragma unroll
            for (int i = 0; i < 8; i++)
#pragma unroll
                for (int j = 0; j < 8; j++) acc[i][j] += xa[i] * yb[j];
        }

        if (more) {
            int nb = buf ^ 1;
            As[nb][kq + 0][r0] = a0.x; As[nb][kq + 1][r0] = a0.y; As[nb][kq + 2][r0] = a0.z; As[nb][kq + 3][r0] = a0.w;
            As[nb][kq + 0][r1] = a1.x; As[nb][kq + 1][r1] = a1.y; As[nb][kq + 2][r1] = a1.z; As[nb][kq + 3][r1] = a1.w;
            Bs[nb][kq + 0][r0] = b0.x; Bs[nb][kq + 1][r0] = b0.y; Bs[nb][kq + 2][r0] = b0.z; Bs[nb][kq + 3][r0] = b0.w;
            Bs[nb][kq + 0][r1] = b1.x; Bs[nb][kq + 1][r1] = b1.y; Bs[nb][kq + 2][r1] = b1.z; Bs[nb][kq + 3][r1] = b1.w;
        }
        __syncthreads();
        buf ^= 1;
    }

    float bc[8];
#pragma unroll
    for (int j = 0; j < 8; j++) {
        int col = bn + tx * 8 + j;
        float v = 0.0f;
        if (bias0) v += bias0[col];
        if (bias1) v += bias1[col];
        bc[j] = v;
    }
#pragma unroll
    for (int i = 0; i < 8; i++) {
        int row = bm + ty * 8 + i;
        float* cp = C + (size_t)row * N + bn + tx * 8;
        float4 o0 = make_float4(acc[i][0] + bc[0], acc[i][1] + bc[1],
                                acc[i][2] + bc[2], acc[i][3] + bc[3]);
        float4 o1 = make_float4(acc[i][4] + bc[4], acc[i][5] + bc[5],
                                acc[i][6] + bc[6], acc[i][7] + bc[7]);
        *(float4*)cp = o0;
        *(float4*)(cp + 4) = o1;
    }
}

// =====================================================================
// LSTM recurrence: one CTA owns 4 batch rows for all T. Thread computes
// gate rows r0=tid (weights in smem, conflict-free) and r1=tid+256
// (weights preloaded into 32 float4 REGISTERS — zero in-loop LDG).
// xp gate biases for t+1 prefetched into registers during step t.
// =====================================================================
#define WPAD 132
#define REC_SMEM (256 * WPAD * 4 + 512 * 4 * 2 + 4 * GG * 4)
__global__ void __launch_bounds__(256, 1) lstm_rec(const float* __restrict__ xp,
                                                   const float* __restrict__ Whh,
                                                   float* __restrict__ hout) {
    extern __shared__ float sm[];
    float* w_s = sm;                     // [256][WPAD]
    float* h_s = w_s + 256 * WPAD;       // [4][128]
    float* c_s = h_s + 512;              // [4][128]
    float* g_s = c_s + 512;              // [4][512]
    int tid = threadIdx.x;
    int b0 = blockIdx.x * 4;

    // per-thread upper weight row (row tid+256) -> registers, loaded once
    float4 w1r[32];
    const float* wg = Whh + (size_t)(256 + tid) * HH;
#pragma unroll
    for (int i = 0; i < 32; i++) w1r[i] = __ldg((const float4*)(wg + 4 * i));

    for (int l = tid; l < 256 * HH; l += 256) {
        int r = l >> 7, k = l & 127;
        w_s[r * WPAD + k] = Whh[r * HH + k];
    }
    for (int l = tid; l < 512; l += 256) { h_s[l] = 0.0f; c_s[l] = 0.0f; }
    __syncthreads();

    const float* w0p = &w_s[tid * WPAD];

    // prefetch xp for t=0
    float xc[8];
    {
        const float* xpt = xp + (size_t)b0 * GG;
#pragma unroll
        for (int bb = 0; bb < 4; bb++) {
            xc[bb]     = xpt[bb * GG + tid];
            xc[4 + bb] = xpt[bb * GG + 256 + tid];
        }
    }

    for (int t = 0; t < TT; t++) {
        float acc0[4], acc1[4];
#pragma unroll
        for (int bb = 0; bb < 4; bb++) { acc0[bb] = xc[bb]; acc1[bb] = xc[4 + bb]; }

        // prefetch next step's xp while we compute
        if (t + 1 < TT) {
            const float* xn = xp + ((size_t)(t + 1) * BB + b0) * GG;
#pragma unroll
            for (int bb = 0; bb < 4; bb++) {
                xc[bb]     = xn[bb * GG + tid];
                xc[4 + bb] = xn[bb * GG + 256 + tid];
            }
        }

#pragma unroll
        for (int k4 = 0; k4 < 32; k4++) {
            float4 w0 = *(const float4*)(w0p + 4 * k4);
            float4 w1 = w1r[k4];
#pragma unroll
            for (int bb = 0; bb < 4; bb++) {
                float4 hb = *(const float4*)&h_s[bb * HH + 4 * k4];
                acc0[bb] += hb.x * w0.x + hb.y * w0.y + hb.z * w0.z + hb.w * w0.w;
                acc1[bb] += hb.x * w1.x + hb.y * w1.y + hb.z * w1.z + hb.w * w1.w;
            }
        }
#pragma unroll
        for (int bb = 0; bb < 4; bb++) {
            g_s[bb * GG + tid]       = acc0[bb];
            g_s[bb * GG + 256 + tid] = acc1[bb];
        }
        __syncthreads();
#pragma unroll
        for (int ii = 0; ii < 2; ii++) {
            int cidx = tid + ii * 256;           // = bb*128 + hh
            int bb = cidx >> 7, hh = cidx & 127;
            float gi = g_s[bb * GG + hh];
            float gf = g_s[bb * GG + 128 + hh];
            float gc = g_s[bb * GG + 256 + hh];
            float go = g_s[bb * GG + 384 + hh];
            float cc = sigf(gf) * c_s[cidx] + sigf(gi) * tanhf(gc);
            float h  = sigf(go) * tanhf(cc);
            c_s[cidx] = cc;
            h_s[cidx] = h;
            hout[((size_t)t * BB + b0 + bb) * HH + hh] = h;
        }
        __syncthreads();
    }
}

// ---------------- attn[n] = sum_h tanh(tmp[n,h]) * v[h] ----------------
__global__ void __launch_bounds__(256) attn_kernel(const float* __restrict__ tmp,
                                                   const float* __restrict__ v) {
    int warp = threadIdx.x >> 5, lane = threadIdx.x & 31;
    int n = blockIdx.x * 8 + warp;
    const float* row = tmp + (size_t)n * HH;
    float s = 0.0f;
#pragma unroll
    for (int j = lane; j < HH; j += 32) s += tanhf(row[j]) * v[j];
#pragma unroll
    for (int o = 16; o; o >>= 1) s += __shfl_xor_sync(0xffffffffu, s, o);
    if (lane == 0) g_attn[n] = s;
}

// ---------------- softmax over T + weighted pool ----------------
__global__ void __launch_bounds__(128) pool_kernel() {
    int b = blockIdx.x;
    int tid = threadIdx.x;
    __shared__ float wt[TT];
    __shared__ float red[128];
    float a = (tid < TT) ? g_attn[tid * BB + b] : -1e30f;
    red[tid] = a;
    __syncthreads();
    for (int s = 64; s; s >>= 1) {
        if (tid < s) red[tid] = fmaxf(red[tid], red[tid + s]);
        __syncthreads();
    }
    float mx = red[0];
    __syncthreads();
    float e = (tid < TT) ? expf(a - mx) : 0.0f;
    red[tid] = e;
    __syncthreads();
    for (int s = 64; s; s >>= 1) {
        if (tid < s) red[tid] += red[tid + s];
        __syncthreads();
    }
    float inv = 1.0f / red[0];
    if (tid < TT) wt[tid] = e * inv;
    __syncthreads();
    float acc = 0.0f;
#pragma unroll 4
    for (int t = 0; t < TT; t++)
        acc += wt[t] * g_h2[((size_t)t * BB + b) * HH + tid];
    g_pooled[b * HH + tid] = acc;
}

// ---------------- head ----------------
__global__ void __launch_bounds__(64) head_kernel(const float* __restrict__ W1,
                                                  const float* __restrict__ b1,
                                                  const float* __restrict__ W2,
                                                  const float* __restrict__ b2,
                                                  float* __restrict__ out) {
    int b = blockIdx.x;
    int tid = threadIdx.x;
    __shared__ float p[HH];
    __shared__ float hdn[64];
    for (int l = tid; l < HH; l += 64) p[l] = g_pooled[b * HH + l];
    __syncthreads();
    float acc = b1[tid];
#pragma unroll 8
    for (int k = 0; k < HH; k++) acc += p[k] * W1[tid * HH + k];
    hdn[tid] = acc;
    __syncthreads();
    if (tid < NC) {
        float o = b2[tid];
#pragma unroll
        for (int k = 0; k < 64; k++) o += hdn[k] * W2[tid * 64 + k];
        out[b * NC + tid] = o;
    }
}

// ---------------- host ----------------
extern "C" void kernel_launch(void* const* d_in, const int* in_sizes, int n_in,
                              void* d_out, int out_size) {
    const float* x      = (const float*)d_in[0];
    const float* conv_w = (const float*)d_in[1];
    const float* conv_b = (const float*)d_in[2];
    const float* Wih0   = (const float*)d_in[3];
    const float* Whh0   = (const float*)d_in[4];
    const float* bih0   = (const float*)d_in[5];
    const float* bhh0   = (const float*)d_in[6];
    const float* Wih1   = (const float*)d_in[7];
    const float* Whh1   = (const float*)d_in[8];
    const float* bih1   = (const float*)d_in[9];
    const float* bhh1   = (const float*)d_in[10];
    const float* W_att  = (const float*)d_in[11];
    const float* b_att  = (const float*)d_in[12];
    const float* v_att  = (const float*)d_in[13];
    const float* W1     = (const float*)d_in[14];
    const float* b1     = (const float*)d_in[15];
    const float* W2     = (const float*)d_in[16];
    const float* b2     = (const float*)d_in[17];
    float* out = (float*)d_out;

    float *seq_p, *xp_p, *h1_p, *h2_p, *wattT_p;
    cudaGetSymbolAddress((void**)&seq_p,   g_seq);
    cudaGetSymbolAddress((void**)&xp_p,    g_xp);
    cudaGetSymbolAddress((void**)&h1_p,    g_h1);
    cudaGetSymbolAddress((void**)&h2_p,    g_h2);
    cudaGetSymbolAddress((void**)&wattT_p, g_wattT);

    cudaFuncSetAttribute(conv_kernel, cudaFuncAttributeMaxDynamicSharedMemorySize,
                         812 * 40 * 4);
    cudaFuncSetAttribute(lstm_rec, cudaFuncAttributeMaxDynamicSharedMemorySize,
                         REC_SMEM);

    // W_att transpose (128x128)
    transpose_kernel<<<(HH * HH + 255) / 256, 256>>>(W_att, wattT_p, HH, HH);

    // conv -> seq
    conv_kernel<<<BB, 256, 812 * 40 * 4>>>(x, conv_w, conv_b);

    // x_proj layer 0: (51200,576) @ Wih0^T + bih0 + bhh0
    gemm128<<<dim3(GG / 128, (TT * BB) / 128), 256>>>(seq_p, Wih0, bih0, bhh0, xp_p,
                                                      TT * BB, GG, FF);
    lstm_rec<<<BB / 4, 256, REC_SMEM>>>(xp_p, Whh0, h1_p);

    // x_proj layer 1
    gemm128<<<dim3(GG / 128, (TT * BB) / 128), 256>>>(h1_p, Wih1, bih1, bhh1, xp_p,
                                                      TT * BB, GG, HH);
    lstm_rec<<<BB / 4, 256, REC_SMEM>>>(xp_p, Whh1, h2_p);

    // attention pre-activation: (51200,128) @ wattT + b_att
    gemm128<<<dim3(HH / 128, (TT * BB) / 128), 256>>>(h2_p, wattT_p, b_att, nullptr,
                                                      xp_p, TT * BB, HH, HH);
    attn_kernel<<<(TT * BB) / 8, 256>>>(xp_p, v_att);
    pool_kernel<<<BB, 128>>>();
    head_kernel<<<BB, 64>>>(W1, b1, W2, b2, out);
}

// round 8
// speedup vs baseline: 1.8101x; 1.8101x over previous
#include <cuda_runtime.h>
#include <cuda_bf16.h>
#include <math.h>
#include <stdint.h>

// ---------------- problem constants ----------------
#define TT   100
#define BB   512
#define WW   18
#define CC   32
#define FF   576
#define HH   128
#define GG   512
#define NC   12

// ---------------- device scratch ----------------
__device__ float g_seq [TT * BB * FF];
__device__ float g_xp  [TT * BB * GG];
__device__ float g_h1  [TT * BB * HH];
__device__ float g_h2  [TT * BB * HH];
__device__ float g_wattT[HH * HH];
__device__ float g_attn [TT * BB];
__device__ float g_pooled[BB * HH];
// bf16 split buffers
__device__ __nv_bfloat16 g_Ahi[TT * BB * FF];
__device__ __nv_bfloat16 g_Alo[TT * BB * FF];
__device__ __nv_bfloat16 g_W0hi[GG * FF], g_W0lo[GG * FF];
__device__ __nv_bfloat16 g_W1hi[GG * HH], g_W1lo[GG * HH];
__device__ __nv_bfloat16 g_Wahi[HH * HH], g_Walo[HH * HH];

__device__ __forceinline__ float sigf(float x) { return 1.0f / (1.0f + expf(-x)); }

__device__ __forceinline__ uint32_t smem_u32(const void* p) {
    uint32_t a;
    asm("{ .reg .u64 t; cvta.to.shared.u64 t, %1; cvt.u32.u64 %0, t; }" : "=r"(a) : "l"(p));
    return a;
}
__device__ __forceinline__ void ldmat4(uint32_t* r, uint32_t addr) {
    asm volatile("ldmatrix.sync.aligned.m8n8.x4.shared.b16 {%0,%1,%2,%3}, [%4];"
                 : "=r"(r[0]), "=r"(r[1]), "=r"(r[2]), "=r"(r[3]) : "r"(addr));
}
__device__ __forceinline__ void mma16816(float* c, const uint32_t* a, const uint32_t* b) {
    asm volatile(
        "mma.sync.aligned.m16n8k16.row.col.f32.bf16.bf16.f32 "
        "{%0,%1,%2,%3}, {%4,%5,%6,%7}, {%8,%9}, {%0,%1,%2,%3};"
        : "+f"(c[0]), "+f"(c[1]), "+f"(c[2]), "+f"(c[3])
        : "r"(a[0]), "r"(a[1]), "r"(a[2]), "r"(a[3]), "r"(b[0]), "r"(b[1]));
}

// =====================================================================
// Conv: one block per batch image (unchanged)
// =====================================================================
__global__ void __launch_bounds__(256, 1) conv_kernel(const float* __restrict__ x,
                                                      const float* __restrict__ cw,
                                                      const float* __restrict__ cb) {
    extern __shared__ float s_img[];
    int b = blockIdx.x;
    int tid = threadIdx.x;
    int wid = tid >> 5, lane = tid & 31;
    int c = lane;

    const float4* src = (const float4*)(x + (size_t)b * 812 * 40);
    float4* dst = (float4*)s_img;
    for (int i = tid; i < 812 * 10; i += 256) dst[i] = src[i];

    float wr[100];
#pragma unroll
    for (int i = 0; i < 100; i++) wr[i] = __ldg(&cw[c * 100 + i]);
    float bv = __ldg(&cb[c]);
    __syncthreads();

    for (int p = wid; p < 50; p += 8) {
        int base_row = 16 * p;
        float acc[2][18];
#pragma unroll
        for (int w = 0; w < 18; w++) { acc[0][w] = bv; acc[1][w] = bv; }
#pragma unroll
        for (int rr = 0; rr < 28; rr++) {
            const float* prow = &s_img[(base_row + rr) * 40];
#pragma unroll
            for (int j = 0; j < 40; j++) {
                float pv = prow[j];
#pragma unroll
                for (int kw = 0; kw < 5; kw++) {
                    int d = j - kw;
                    if (d >= 0 && (d & 1) == 0) {
                        int w = d >> 1;
                        if (w < 18) {
                            if (rr < 20) acc[0][w] += wr[rr * 5 + kw] * pv;
                            if (rr >= 8) acc[1][w] += wr[(rr - 8) * 5 + kw] * pv;
                        }
                    }
                }
            }
        }
#pragma unroll
        for (int ts = 0; ts < 2; ts++) {
            int t = 2 * p + ts;
            float* out = &g_seq[((size_t)t * BB + b) * FF];
#pragma unroll
            for (int w = 0; w < 18; w++)
                out[w * 32 + c] = fmaxf(acc[ts][w], 0.0f);
        }
    }
}

// ---------------- transpose (W_att) ----------------
__global__ void transpose_kernel(const float* __restrict__ in, float* __restrict__ out,
                                 int rows, int cols) {
    int idx = blockIdx.x * 256 + threadIdx.x;
    if (idx < rows * cols) {
        int r = idx / cols, c = idx % cols;
        out[c * rows + r] = in[idx];
    }
}

// ---------------- fp32 -> bf16 hi/lo split ----------------
__global__ void __launch_bounds__(256) split_kernel(const float* __restrict__ in,
                                                    __nv_bfloat16* __restrict__ hi,
                                                    __nv_bfloat16* __restrict__ lo,
                                                    int n4) {
    int i = blockIdx.x * 256 + threadIdx.x;
    if (i >= n4) return;
    float4 v = ((const float4*)in)[i];
    __nv_bfloat16 h0 = __float2bfloat16(v.x), h1 = __float2bfloat16(v.y);
    __nv_bfloat16 h2 = __float2bfloat16(v.z), h3 = __float2bfloat16(v.w);
    __nv_bfloat16 l0 = __float2bfloat16(v.x - __bfloat162float(h0));
    __nv_bfloat16 l1 = __float2bfloat16(v.y - __bfloat162float(h1));
    __nv_bfloat16 l2 = __float2bfloat16(v.z - __bfloat162float(h2));
    __nv_bfloat16 l3 = __float2bfloat16(v.w - __bfloat162float(h3));
    __nv_bfloat162* hp = (__nv_bfloat162*)hi;
    __nv_bfloat162* lp = (__nv_bfloat162*)lo;
    hp[2 * i]     = __nv_bfloat162(h0, h1);
    hp[2 * i + 1] = __nv_bfloat162(h2, h3);
    lp[2 * i]     = __nv_bfloat162(l0, l1);
    lp[2 * i + 1] = __nv_bfloat162(l2, l3);
}

// =====================================================================
// bf16-split GEMM via mma.sync.m16n8k16 (baseline PTX, no sm_103a feats)
// C[M,N] = Ahi@Bhi^T + Alo@Bhi^T + Ahi@Blo^T + bias0(+bias1)
// CTA 128x128, 256 thr (warps 2x4, warp tile 64x32), K-chunk 32.
// smem tiles [128][40] bf16 (80B stride -> ldmatrix conflict-free).
// =====================================================================
#define ASTR 40

__global__ void __launch_bounds__(256) gemm_mma(const __nv_bfloat16* __restrict__ Ahi,
                                                const __nv_bfloat16* __restrict__ Alo,
                                                const __nv_bfloat16* __restrict__ Bhi,
                                                const __nv_bfloat16* __restrict__ Blo,
                                                const float* __restrict__ bias0,
                                                const float* __restrict__ bias1,
                                                float* __restrict__ C,
                                                int M, int N, int K) {
    __shared__ __nv_bfloat16 sAhi[128 * ASTR], sAlo[128 * ASTR];
    __shared__ __nv_bfloat16 sBhi[128 * ASTR], sBlo[128 * ASTR];

    int tid = threadIdx.x;
    int warp = tid >> 5, lane = tid & 31;
    int wm = warp >> 2, wn = warp & 3;
    int bm = blockIdx.y * 128, bn = blockIdx.x * 128;

    // global load mapping: 2 x uint4 per tile per thread
    int lrow0 = tid >> 1;                 // rows 0..127 (2 threads per row)
    int lseg0 = (tid & 1) * 2;            // segments {0,1} or {2,3} (8 bf16 each)
    const __nv_bfloat16* pAhi = Ahi + (size_t)(bm + lrow0) * K + lseg0 * 8;
    const __nv_bfloat16* pAlo = Alo + (size_t)(bm + lrow0) * K + lseg0 * 8;
    const __nv_bfloat16* pBhi = Bhi + (size_t)(bn + lrow0) * K + lseg0 * 8;
    const __nv_bfloat16* pBlo = Blo + (size_t)(bn + lrow0) * K + lseg0 * 8;

    float acc[4][4][4];
#pragma unroll
    for (int i = 0; i < 4; i++)
#pragma unroll
        for (int j = 0; j < 4; j++)
#pragma unroll
            for (int q = 0; q < 4; q++) acc[i][j][q] = 0.0f;

    uint32_t aAhi = smem_u32(sAhi), aAlo = smem_u32(sAlo);
    uint32_t aBhi = smem_u32(sBhi), aBlo = smem_u32(sBlo);

    // ldmatrix addresses (constant per thread up to k offset)
    // A: row = wm*64 + mi*16 + (lane&15), col byte = (ko + (lane>>4)*8)*2
    uint32_t aRow = (uint32_t)(wm * 64 + (lane & 15));
    uint32_t aColHalf = (uint32_t)((lane >> 4) * 8);
    // B: group = lane>>3, row = wn*32 + np*16 + (group>=2)*8 + (lane&7), col = ko + (group&1)*8
    uint32_t g = (uint32_t)(lane >> 3);
    uint32_t bRow = (uint32_t)(wn * 32 + ((g >> 1) * 8) + (lane & 7));
    uint32_t bColHalf = (g & 1) * 8;

    uint4 ra0, ra1, rb0, rb1, rc0, rc1, rd0, rd1;
    ra0 = *(const uint4*)pAhi;       ra1 = *(const uint4*)(pAhi + 8);
    rb0 = *(const uint4*)pAlo;       rb1 = *(const uint4*)(pAlo + 8);
    rc0 = *(const uint4*)pBhi;       rc1 = *(const uint4*)(pBhi + 8);
    rd0 = *(const uint4*)pBlo;       rd1 = *(const uint4*)(pBlo + 8);

    int nchunks = K >> 5;
    for (int c0 = 0; c0 < nchunks; c0++) {
        // store staged regs to smem
        {
            uint4* d;
            d = (uint4*)&sAhi[lrow0 * ASTR + lseg0 * 8]; d[0] = ra0; d[1] = ra1;
            d = (uint4*)&sAlo[lrow0 * ASTR + lseg0 * 8]; d[0] = rb0; d[1] = rb1;
            d = (uint4*)&sBhi[lrow0 * ASTR + lseg0 * 8]; d[0] = rc0; d[1] = rc1;
            d = (uint4*)&sBlo[lrow0 * ASTR + lseg0 * 8]; d[0] = rd0; d[1] = rd1;
        }
        __syncthreads();

        // prefetch next chunk
        if (c0 + 1 < nchunks) {
            int kn = (c0 + 1) << 5;
            ra0 = *(const uint4*)(pAhi + kn);  ra1 = *(const uint4*)(pAhi + kn + 8);
            rb0 = *(const uint4*)(pAlo + kn);  rb1 = *(const uint4*)(pAlo + kn + 8);
            rc0 = *(const uint4*)(pBhi + kn);  rc1 = *(const uint4*)(pBhi + kn + 8);
            rd0 = *(const uint4*)(pBlo + kn);  rd1 = *(const uint4*)(pBlo + kn + 8);
        }

#pragma unroll
        for (int ko = 0; ko < 32; ko += 16) {
            uint32_t fahi[4][4], falo[4][4], fbhi[2][4], fblo[2][4];
#pragma unroll
            for (int mi = 0; mi < 4; mi++) {
                uint32_t off = ((aRow + mi * 16) * ASTR + ko + aColHalf) * 2;
                ldmat4(fahi[mi], aAhi + off);
                ldmat4(falo[mi], aAlo + off);
            }
#pragma unroll
            for (int np = 0; np < 2; np++) {
                uint32_t off = ((bRow + np * 16) * ASTR + ko + bColHalf) * 2;
                ldmat4(fbhi[np], aBhi + off);
                ldmat4(fblo[np], aBlo + off);
            }
#pragma unroll
            for (int mi = 0; mi < 4; mi++) {
#pragma unroll
                for (int nt = 0; nt < 4; nt++) {
                    int np = nt >> 1, hf = (nt & 1) * 2;
                    uint32_t bh[2] = { fbhi[np][hf], fbhi[np][hf + 1] };
                    uint32_t bl[2] = { fblo[np][hf], fblo[np][hf + 1] };
                    mma16816(acc[mi][nt], fahi[mi], bh);
                    mma16816(acc[mi][nt], falo[mi], bh);
                    mma16816(acc[mi][nt], fahi[mi], bl);
                }
            }
        }
        __syncthreads();
    }

    // epilogue: direct stores (float2), add biases
#pragma unroll
    for (int nt = 0; nt < 4; nt++) {
        int col = bn + wn * 32 + nt * 8 + (lane & 3) * 2;
        float bv0 = 0.0f, bv1 = 0.0f;
        if (bias0) { bv0 += bias0[col]; bv1 += bias0[col + 1]; }
        if (bias1) { bv0 += bias1[col]; bv1 += bias1[col + 1]; }
#pragma unroll
        for (int mi = 0; mi < 4; mi++) {
            int row = bm + wm * 64 + mi * 16 + (lane >> 2);
            float2 v0 = make_float2(acc[mi][nt][0] + bv0, acc[mi][nt][1] + bv1);
            float2 v1 = make_float2(acc[mi][nt][2] + bv0, acc[mi][nt][3] + bv1);
            *(float2*)&C[(size_t)row * N + col] = v0;
            *(float2*)&C[(size_t)(row + 8) * N + col] = v1;
        }
    }
}

// =====================================================================
// LSTM recurrence (round-5 version)
// =====================================================================
#define WPAD 132
#define REC_SMEM (256 * WPAD * 4 + 512 * 4 * 2 + 4 * GG * 4)
__global__ void __launch_bounds__(256, 1) lstm_rec(const float* __restrict__ xp,
                                                   const float* __restrict__ Whh,
                                                   float* __restrict__ hout) {
    extern __shared__ float sm[];
    float* w_s = sm;
    float* h_s = w_s + 256 * WPAD;
    float* c_s = h_s + 512;
    float* g_s = c_s + 512;
    int tid = threadIdx.x;
    int b0 = blockIdx.x * 4;

    float4 w1r[32];
    const float* wg = Whh + (size_t)(256 + tid) * HH;
#pragma unroll
    for (int i = 0; i < 32; i++) w1r[i] = __ldg((const float4*)(wg + 4 * i));

    for (int l = tid; l < 256 * HH; l += 256) {
        int r = l >> 7, k = l & 127;
        w_s[r * WPAD + k] = Whh[r * HH + k];
    }
    for (int l = tid; l < 512; l += 256) { h_s[l] = 0.0f; c_s[l] = 0.0f; }
    __syncthreads();

    const float* w0p = &w_s[tid * WPAD];

    float xc[8];
    {
        const float* xpt = xp + (size_t)b0 * GG;
#pragma unroll
        for (int bb = 0; bb < 4; bb++) {
            xc[bb]     = xpt[bb * GG + tid];
            xc[4 + bb] = xpt[bb * GG + 256 + tid];
        }
    }

    for (int t = 0; t < TT; t++) {
        float acc0[4], acc1[4];
#pragma unroll
        for (int bb = 0; bb < 4; bb++) { acc0[bb] = xc[bb]; acc1[bb] = xc[4 + bb]; }

        if (t + 1 < TT) {
            const float* xn = xp + ((size_t)(t + 1) * BB + b0) * GG;
#pragma unroll
            for (int bb = 0; bb < 4; bb++) {
                xc[bb]     = xn[bb * GG + tid];
                xc[4 + bb] = xn[bb * GG + 256 + tid];
            }
        }

#pragma unroll
        for (int k4 = 0; k4 < 32; k4++) {
            float4 w0 = *(const float4*)(w0p + 4 * k4);
            float4 w1 = w1r[k4];
#pragma unroll
            for (int bb = 0; bb < 4; bb++) {
                float4 hb = *(const float4*)&h_s[bb * HH + 4 * k4];
                acc0[bb] += hb.x * w0.x + hb.y * w0.y + hb.z * w0.z + hb.w * w0.w;
                acc1[bb] += hb.x * w1.x + hb.y * w1.y + hb.z * w1.z + hb.w * w1.w;
            }
        }
#pragma unroll
        for (int bb = 0; bb < 4; bb++) {
            g_s[bb * GG + tid]       = acc0[bb];
            g_s[bb * GG + 256 + tid] = acc1[bb];
        }
        __syncthreads();
#pragma unroll
        for (int ii = 0; ii < 2; ii++) {
            int cidx = tid + ii * 256;
            int bb = cidx >> 7, hh = cidx & 127;
            float gi = g_s[bb * GG + hh];
            float gf = g_s[bb * GG + 128 + hh];
            float gc = g_s[bb * GG + 256 + hh];
            float go = g_s[bb * GG + 384 + hh];
            float cc = sigf(gf) * c_s[cidx] + sigf(gi) * tanhf(gc);
            float h  = sigf(go) * tanhf(cc);
            c_s[cidx] = cc;
            h_s[cidx] = h;
            hout[((size_t)t * BB + b0 + bb) * HH + hh] = h;
        }
        __syncthreads();
    }
}

// ---------------- attn ----------------
__global__ void __launch_bounds__(256) attn_kernel(const float* __restrict__ tmp,
                                                   const float* __restrict__ v) {
    int warp = threadIdx.x >> 5, lane = threadIdx.x & 31;
    int n = blockIdx.x * 8 + warp;
    const float* row = tmp + (size_t)n * HH;
    float s = 0.0f;
#pragma unroll
    for (int j = lane; j < HH; j += 32) s += tanhf(row[j]) * v[j];
#pragma unroll
    for (int o = 16; o; o >>= 1) s += __shfl_xor_sync(0xffffffffu, s, o);
    if (lane == 0) g_attn[n] = s;
}

// ---------------- softmax + pool ----------------
__global__ void __launch_bounds__(128) pool_kernel() {
    int b = blockIdx.x;
    int tid = threadIdx.x;
    __shared__ float wt[TT];
    __shared__ float red[128];
    float a = (tid < TT) ? g_attn[tid * BB + b] : -1e30f;
    red[tid] = a;
    __syncthreads();
    for (int s = 64; s; s >>= 1) {
        if (tid < s) red[tid] = fmaxf(red[tid], red[tid + s]);
        __syncthreads();
    }
    float mx = red[0];
    __syncthreads();
    float e = (tid < TT) ? expf(a - mx) : 0.0f;
    red[tid] = e;
    __syncthreads();
    for (int s = 64; s; s >>= 1) {
        if (tid < s) red[tid] += red[tid + s];
        __syncthreads();
    }
    float inv = 1.0f / red[0];
    if (tid < TT) wt[tid] = e * inv;
    __syncthreads();
    float acc = 0.0f;
#pragma unroll 4
    for (int t = 0; t < TT; t++)
        acc += wt[t] * g_h2[((size_t)t * BB + b) * HH + tid];
    g_pooled[b * HH + tid] = acc;
}

// ---------------- head ----------------
__global__ void __launch_bounds__(64) head_kernel(const float* __restrict__ W1,
                                                  const float* __restrict__ b1,
                                                  const float* __restrict__ W2,
                                                  const float* __restrict__ b2,
                                                  float* __restrict__ out) {
    int b = blockIdx.x;
    int tid = threadIdx.x;
    __shared__ float p[HH];
    __shared__ float hdn[64];
    for (int l = tid; l < HH; l += 64) p[l] = g_pooled[b * HH + l];
    __syncthreads();
    float acc = b1[tid];
#pragma unroll 8
    for (int k = 0; k < HH; k++) acc += p[k] * W1[tid * HH + k];
    hdn[tid] = acc;
    __syncthreads();
    if (tid < NC) {
        float o = b2[tid];
#pragma unroll
        for (int k = 0; k < 64; k++) o += hdn[k] * W2[tid * 64 + k];
        out[b * NC + tid] = o;
    }
}

// ---------------- host ----------------
extern "C" void kernel_launch(void* const* d_in, const int* in_sizes, int n_in,
                              void* d_out, int out_size) {
    const float* x      = (const float*)d_in[0];
    const float* conv_w = (const float*)d_in[1];
    const float* conv_b = (const float*)d_in[2];
    const float* Wih0   = (const float*)d_in[3];
    const float* Whh0   = (const float*)d_in[4];
    const float* bih0   = (const float*)d_in[5];
    const float* bhh0   = (const float*)d_in[6];
    const float* Wih1   = (const float*)d_in[7];
    const float* Whh1   = (const float*)d_in[8];
    const float* bih1   = (const float*)d_in[9];
    const float* bhh1   = (const float*)d_in[10];
    const float* W_att  = (const float*)d_in[11];
    const float* b_att  = (const float*)d_in[12];
    const float* v_att  = (const float*)d_in[13];
    const float* W1     = (const float*)d_in[14];
    const float* b1     = (const float*)d_in[15];
    const float* W2     = (const float*)d_in[16];
    const float* b2     = (const float*)d_in[17];
    float* out = (float*)d_out;

    float *seq_p, *xp_p, *h1_p, *h2_p, *wattT_p;
    __nv_bfloat16 *Ahi_p, *Alo_p, *W0hi_p, *W0lo_p, *W1hi_p, *W1lo_p, *Wahi_p, *Walo_p;
    cudaGetSymbolAddress((void**)&seq_p,   g_seq);
    cudaGetSymbolAddress((void**)&xp_p,    g_xp);
    cudaGetSymbolAddress((void**)&h1_p,    g_h1);
    cudaGetSymbolAddress((void**)&h2_p,    g_h2);
    cudaGetSymbolAddress((void**)&wattT_p, g_wattT);
    cudaGetSymbolAddress((void**)&Ahi_p,  g_Ahi);
    cudaGetSymbolAddress((void**)&Alo_p,  g_Alo);
    cudaGetSymbolAddress((void**)&W0hi_p, g_W0hi);
    cudaGetSymbolAddress((void**)&W0lo_p, g_W0lo);
    cudaGetSymbolAddress((void**)&W1hi_p, g_W1hi);
    cudaGetSymbolAddress((void**)&W1lo_p, g_W1lo);
    cudaGetSymbolAddress((void**)&Wahi_p, g_Wahi);
    cudaGetSymbolAddress((void**)&Walo_p, g_Walo);

    cudaFuncSetAttribute(conv_kernel, cudaFuncAttributeMaxDynamicSharedMemorySize,
                         812 * 40 * 4);
    cudaFuncSetAttribute(lstm_rec, cudaFuncAttributeMaxDynamicSharedMemorySize,
                         REC_SMEM);

    const int M = TT * BB;   // 51200

    // weight prep
    transpose_kernel<<<(HH * HH + 255) / 256, 256>>>(W_att, wattT_p, HH, HH);
    split_kernel<<<(GG * FF / 4 + 255) / 256, 256>>>(Wih0, W0hi_p, W0lo_p, GG * FF / 4);
    split_kernel<<<(GG * HH / 4 + 255) / 256, 256>>>(Wih1, W1hi_p, W1lo_p, GG * HH / 4);
    split_kernel<<<(HH * HH / 4 + 255) / 256, 256>>>(wattT_p, Wahi_p, Walo_p, HH * HH / 4);

    // conv -> seq, split
    conv_kernel<<<BB, 256, 812 * 40 * 4>>>(x, conv_w, conv_b);
    split_kernel<<<(M * FF / 4 + 255) / 256, 256>>>(seq_p, Ahi_p, Alo_p, M * FF / 4);

    // layer 0
    gemm_mma<<<dim3(GG / 128, M / 128), 256>>>(Ahi_p, Alo_p, W0hi_p, W0lo_p,
                                               bih0, bhh0, xp_p, M, GG, FF);
    lstm_rec<<<BB / 4, 256, REC_SMEM>>>(xp_p, Whh0, h1_p);

    // layer 1
    split_kernel<<<(M * HH / 4 + 255) / 256, 256>>>(h1_p, Ahi_p, Alo_p, M * HH / 4);
    gemm_mma<<<dim3(GG / 128, M / 128), 256>>>(Ahi_p, Alo_p, W1hi_p, W1lo_p,
                                               bih1, bhh1, xp_p, M, GG, HH);
    lstm_rec<<<BB / 4, 256, REC_SMEM>>>(xp_p, Whh1, h2_p);

    // attention
    split_kernel<<<(M * HH / 4 + 255) / 256, 256>>>(h2_p, Ahi_p, Alo_p, M * HH / 4);
    gemm_mma<<<dim3(HH / 128, M / 128), 256>>>(Ahi_p, Alo_p, Wahi_p, Walo_p,
                                               b_att, nullptr, xp_p, M, HH, HH);
    attn_kernel<<<(M) / 8, 256>>>(xp_p, v_att);
    pool_kernel<<<BB, 128>>>();
    head_kernel<<<BB, 64>>>(W1, b1, W2, b2, out);
}

// round 9
// speedup vs baseline: 1.9412x; 1.0724x over previous
#include <cuda_runtime.h>
#include <cuda_bf16.h>
#include <math.h>
#include <stdint.h>

// ---------------- problem constants ----------------
#define TT   100
#define BB   512
#define WW   18
#define CC   32
#define FF   576
#define HH   128
#define GG   512
#define NC   12

// ---------------- device scratch ----------------
__device__ float g_xp  [TT * BB * GG];
__device__ float g_h2  [TT * BB * HH];
__device__ float g_wattT[HH * HH];
__device__ float g_attn [TT * BB];
__device__ float g_pooled[BB * HH];
// bf16 split buffers
__device__ __nv_bfloat16 g_Ahi[TT * BB * FF];
__device__ __nv_bfloat16 g_Alo[TT * BB * FF];
__device__ __nv_bfloat16 g_W0hi[GG * FF], g_W0lo[GG * FF];
__device__ __nv_bfloat16 g_W1hi[GG * HH], g_W1lo[GG * HH];
__device__ __nv_bfloat16 g_Wahi[HH * HH], g_Walo[HH * HH];

// fast, accurate-enough activations (EX2/RCP approx: rel err ~2e-7)
__device__ __forceinline__ float ftanh(float x) {
    float xc = fminf(fmaxf(x, -9.0f), 9.0f);
    float t = __expf(2.0f * xc);
    return __fdividef(t - 1.0f, t + 1.0f);
}
__device__ __forceinline__ float fsig(float x) {
    return __fdividef(1.0f, 1.0f + __expf(-x));
}

__device__ __forceinline__ uint32_t smem_u32(const void* p) {
    uint32_t a;
    asm("{ .reg .u64 t; cvta.to.shared.u64 t, %1; cvt.u32.u64 %0, t; }" : "=r"(a) : "l"(p));
    return a;
}
__device__ __forceinline__ void ldmat4(uint32_t* r, uint32_t addr) {
    asm volatile("ldmatrix.sync.aligned.m8n8.x4.shared.b16 {%0,%1,%2,%3}, [%4];"
                 : "=r"(r[0]), "=r"(r[1]), "=r"(r[2]), "=r"(r[3]) : "r"(addr));
}
__device__ __forceinline__ void mma16816(float* c, const uint32_t* a, const uint32_t* b) {
    asm volatile(
        "mma.sync.aligned.m16n8k16.row.col.f32.bf16.bf16.f32 "
        "{%0,%1,%2,%3}, {%4,%5,%6,%7}, {%8,%9}, {%0,%1,%2,%3};"
        : "+f"(c[0]), "+f"(c[1]), "+f"(c[2]), "+f"(c[3])
        : "r"(a[0]), "r"(a[1]), "r"(a[2]), "r"(a[3]), "r"(b[0]), "r"(b[1]));
}

// =====================================================================
// Conv: one block per batch image; writes bf16 hi/lo split DIRECTLY.
// =====================================================================
__global__ void __launch_bounds__(256, 1) conv_kernel(const float* __restrict__ x,
                                                      const float* __restrict__ cw,
                                                      const float* __restrict__ cb) {
    extern __shared__ float s_img[];
    int b = blockIdx.x;
    int tid = threadIdx.x;
    int wid = tid >> 5, lane = tid & 31;
    int c = lane;

    const float4* src = (const float4*)(x + (size_t)b * 812 * 40);
    float4* dst = (float4*)s_img;
    for (int i = tid; i < 812 * 10; i += 256) dst[i] = src[i];

    float wr[100];
#pragma unroll
    for (int i = 0; i < 100; i++) wr[i] = __ldg(&cw[c * 100 + i]);
    float bv = __ldg(&cb[c]);
    __syncthreads();

    for (int p = wid; p < 50; p += 8) {
        int base_row = 16 * p;
        float acc[2][18];
#pragma unroll
        for (int w = 0; w < 18; w++) { acc[0][w] = bv; acc[1][w] = bv; }
#pragma unroll
        for (int rr = 0; rr < 28; rr++) {
            const float* prow = &s_img[(base_row + rr) * 40];
#pragma unroll
            for (int j = 0; j < 40; j++) {
                float pv = prow[j];
#pragma unroll
                for (int kw = 0; kw < 5; kw++) {
                    int d = j - kw;
                    if (d >= 0 && (d & 1) == 0) {
                        int w = d >> 1;
                        if (w < 18) {
                            if (rr < 20) acc[0][w] += wr[rr * 5 + kw] * pv;
                            if (rr >= 8) acc[1][w] += wr[(rr - 8) * 5 + kw] * pv;
                        }
                    }
                }
            }
        }
#pragma unroll
        for (int ts = 0; ts < 2; ts++) {
            int t = 2 * p + ts;
            size_t base = ((size_t)t * BB + b) * FF + c;
#pragma unroll
            for (int w = 0; w < 18; w++) {
                float v = fmaxf(acc[ts][w], 0.0f);
                __nv_bfloat16 h = __float2bfloat16(v);
                __nv_bfloat16 l = __float2bfloat16(v - __bfloat162float(h));
                g_Ahi[base + w * 32] = h;
                g_Alo[base + w * 32] = l;
            }
        }
    }
}

// ---------------- transpose (W_att) ----------------
__global__ void transpose_kernel(const float* __restrict__ in, float* __restrict__ out,
                                 int rows, int cols) {
    int idx = blockIdx.x * 256 + threadIdx.x;
    if (idx < rows * cols) {
        int r = idx / cols, c = idx % cols;
        out[c * rows + r] = in[idx];
    }
}

// ---------------- fp32 -> bf16 hi/lo split (weights only) ----------------
__global__ void __launch_bounds__(256) split_kernel(const float* __restrict__ in,
                                                    __nv_bfloat16* __restrict__ hi,
                                                    __nv_bfloat16* __restrict__ lo,
                                                    int n4) {
    int i = blockIdx.x * 256 + threadIdx.x;
    if (i >= n4) return;
    float4 v = ((const float4*)in)[i];
    __nv_bfloat16 h0 = __float2bfloat16(v.x), h1 = __float2bfloat16(v.y);
    __nv_bfloat16 h2 = __float2bfloat16(v.z), h3 = __float2bfloat16(v.w);
    __nv_bfloat16 l0 = __float2bfloat16(v.x - __bfloat162float(h0));
    __nv_bfloat16 l1 = __float2bfloat16(v.y - __bfloat162float(h1));
    __nv_bfloat16 l2 = __float2bfloat16(v.z - __bfloat162float(h2));
    __nv_bfloat16 l3 = __float2bfloat16(v.w - __bfloat162float(h3));
    __nv_bfloat162* hp = (__nv_bfloat162*)hi;
    __nv_bfloat162* lp = (__nv_bfloat162*)lo;
    hp[2 * i]     = __nv_bfloat162(h0, h1);
    hp[2 * i + 1] = __nv_bfloat162(h2, h3);
    lp[2 * i]     = __nv_bfloat162(l0, l1);
    lp[2 * i + 1] = __nv_bfloat162(l2, l3);
}

// =====================================================================
// bf16-split GEMM via mma.sync.m16n8k16 (unchanged from round 8)
// =====================================================================
#define ASTR 40

__global__ void __launch_bounds__(256) gemm_mma(const __nv_bfloat16* __restrict__ Ahi,
                                                const __nv_bfloat16* __restrict__ Alo,
                                                const __nv_bfloat16* __restrict__ Bhi,
                                                const __nv_bfloat16* __restrict__ Blo,
                                                const float* __restrict__ bias0,
                                                const float* __restrict__ bias1,
                                                float* __restrict__ C,
                                                int M, int N, int K) {
    __shared__ __nv_bfloat16 sAhi[128 * ASTR], sAlo[128 * ASTR];
    __shared__ __nv_bfloat16 sBhi[128 * ASTR], sBlo[128 * ASTR];

    int tid = threadIdx.x;
    int warp = tid >> 5, lane = tid & 31;
    int wm = warp >> 2, wn = warp & 3;
    int bm = blockIdx.y * 128, bn = blockIdx.x * 128;

    int lrow0 = tid >> 1;
    int lseg0 = (tid & 1) * 2;
    const __nv_bfloat16* pAhi = Ahi + (size_t)(bm + lrow0) * K + lseg0 * 8;
    const __nv_bfloat16* pAlo = Alo + (size_t)(bm + lrow0) * K + lseg0 * 8;
    const __nv_bfloat16* pBhi = Bhi + (size_t)(bn + lrow0) * K + lseg0 * 8;
    const __nv_bfloat16* pBlo = Blo + (size_t)(bn + lrow0) * K + lseg0 * 8;

    float acc[4][4][4];
#pragma unroll
    for (int i = 0; i < 4; i++)
#pragma unroll
        for (int j = 0; j < 4; j++)
#pragma unroll
            for (int q = 0; q < 4; q++) acc[i][j][q] = 0.0f;

    uint32_t aAhi = smem_u32(sAhi), aAlo = smem_u32(sAlo);
    uint32_t aBhi = smem_u32(sBhi), aBlo = smem_u32(sBlo);

    uint32_t aRow = (uint32_t)(wm * 64 + (lane & 15));
    uint32_t aColHalf = (uint32_t)((lane >> 4) * 8);
    uint32_t g = (uint32_t)(lane >> 3);
    uint32_t bRow = (uint32_t)(wn * 32 + ((g >> 1) * 8) + (lane & 7));
    uint32_t bColHalf = (g & 1) * 8;

    uint4 ra0, ra1, rb0, rb1, rc0, rc1, rd0, rd1;
    ra0 = *(const uint4*)pAhi;       ra1 = *(const uint4*)(pAhi + 8);
    rb0 = *(const uint4*)pAlo;       rb1 = *(const uint4*)(pAlo + 8);
    rc0 = *(const uint4*)pBhi;       rc1 = *(const uint4*)(pBhi + 8);
    rd0 = *(const uint4*)pBlo;       rd1 = *(const uint4*)(pBlo + 8);

    int nchunks = K >> 5;
    for (int c0 = 0; c0 < nchunks; c0++) {
        {
            uint4* d;
            d = (uint4*)&sAhi[lrow0 * ASTR + lseg0 * 8]; d[0] = ra0; d[1] = ra1;
            d = (uint4*)&sAlo[lrow0 * ASTR + lseg0 * 8]; d[0] = rb0; d[1] = rb1;
            d = (uint4*)&sBhi[lrow0 * ASTR + lseg0 * 8]; d[0] = rc0; d[1] = rc1;
            d = (uint4*)&sBlo[lrow0 * ASTR + lseg0 * 8]; d[0] = rd0; d[1] = rd1;
        }
        __syncthreads();

        if (c0 + 1 < nchunks) {
            int kn = (c0 + 1) << 5;
            ra0 = *(const uint4*)(pAhi + kn);  ra1 = *(const uint4*)(pAhi + kn + 8);
            rb0 = *(const uint4*)(pAlo + kn);  rb1 = *(const uint4*)(pAlo + kn + 8);
            rc0 = *(const uint4*)(pBhi + kn);  rc1 = *(const uint4*)(pBhi + kn + 8);
            rd0 = *(const uint4*)(pBlo + kn);  rd1 = *(const uint4*)(pBlo + kn + 8);
        }

#pragma unroll
        for (int ko = 0; ko < 32; ko += 16) {
            uint32_t fahi[4][4], falo[4][4], fbhi[2][4], fblo[2][4];
#pragma unroll
            for (int mi = 0; mi < 4; mi++) {
                uint32_t off = ((aRow + mi * 16) * ASTR + ko + aColHalf) * 2;
                ldmat4(fahi[mi], aAhi + off);
                ldmat4(falo[mi], aAlo + off);
            }
#pragma unroll
            for (int np = 0; np < 2; np++) {
                uint32_t off = ((bRow + np * 16) * ASTR + ko + bColHalf) * 2;
                ldmat4(fbhi[np], aBhi + off);
                ldmat4(fblo[np], aBlo + off);
            }
#pragma unroll
            for (int mi = 0; mi < 4; mi++) {
#pragma unroll
                for (int nt = 0; nt < 4; nt++) {
                    int np = nt >> 1, hf = (nt & 1) * 2;
                    uint32_t bh[2] = { fbhi[np][hf], fbhi[np][hf + 1] };
                    uint32_t bl[2] = { fblo[np][hf], fblo[np][hf + 1] };
                    mma16816(acc[mi][nt], fahi[mi], bh);
                    mma16816(acc[mi][nt], falo[mi], bh);
                    mma16816(acc[mi][nt], fahi[mi], bl);
                }
            }
        }
        __syncthreads();
    }

#pragma unroll
    for (int nt = 0; nt < 4; nt++) {
        int col = bn + wn * 32 + nt * 8 + (lane & 3) * 2;
        float bv0 = 0.0f, bv1 = 0.0f;
        if (bias0) { bv0 += bias0[col]; bv1 += bias0[col + 1]; }
        if (bias1) { bv0 += bias1[col]; bv1 += bias1[col + 1]; }
#pragma unroll
        for (int mi = 0; mi < 4; mi++) {
            int row = bm + wm * 64 + mi * 16 + (lane >> 2);
            float2 v0 = make_float2(acc[mi][nt][0] + bv0, acc[mi][nt][1] + bv1);
            float2 v1 = make_float2(acc[mi][nt][2] + bv0, acc[mi][nt][3] + bv1);
            *(float2*)&C[(size_t)row * N + col] = v0;
            *(float2*)&C[(size_t)(row + 8) * N + col] = v1;
        }
    }
}

// =====================================================================
// LSTM recurrence, 512 threads: thread = (gate-row pair, k-half).
// t8 = tid&255 -> rows t8 (smem weights) and t8+256 (reg weights, 64 fl);
// kh = tid>>8 -> k in [kh*64, kh*64+64). Partials combined in gate phase.
// Epilogue writes bf16 hi/lo (next GEMM input) + optional fp32 h.
// =====================================================================
#define WPAD 132
#define REC_SMEM ((256 * WPAD + 512 + 512 + 4096) * 4)
__global__ void __launch_bounds__(512, 1) lstm_rec(const float* __restrict__ xp,
                                                   const float* __restrict__ Whh,
                                                   float* __restrict__ houtf,
                                                   __nv_bfloat16* __restrict__ hhi,
                                                   __nv_bfloat16* __restrict__ hlo) {
    extern __shared__ float sm[];
    float* w_s = sm;                     // [256][WPAD]
    float* h_s = w_s + 256 * WPAD;       // [512]  (bb*128+hh)
    float* c_s = h_s + 512;              // [512]
    float* gp  = c_s + 512;              // [2][4][512] partials
    int tid = threadIdx.x;
    int t8 = tid & 255, kh = tid >> 8;
    int k0 = kh * 64;
    int b0 = blockIdx.x * 4;

    // upper-row reg weights: row t8+256, k slice [k0, k0+64)
    float4 w1r[16];
    const float* wg = Whh + (size_t)(256 + t8) * HH + k0;
#pragma unroll
    for (int i = 0; i < 16; i++) w1r[i] = __ldg((const float4*)(wg + 4 * i));

    for (int l = tid; l < 256 * HH; l += 512) {
        int r = l >> 7, k = l & 127;
        w_s[r * WPAD + k] = Whh[r * HH + k];
    }
    if (tid < 512) { h_s[tid] = 0.0f; c_s[tid] = 0.0f; }
    __syncthreads();

    const float* w0p = &w_s[t8 * WPAD + k0];

    // xp prefetch for t=0: kh=0 threads carry row t8 bias, kh=1 carry row t8+256
    int xrow = t8 + kh * 256;
    float xc[4];
    {
        const float* xpt = xp + (size_t)b0 * GG + xrow;
#pragma unroll
        for (int bb = 0; bb < 4; bb++) xc[bb] = xpt[bb * GG];
    }

    for (int t = 0; t < TT; t++) {
        float acc0[4], acc1[4];
#pragma unroll
        for (int bb = 0; bb < 4; bb++) {
            acc0[bb] = (kh == 0) ? xc[bb] : 0.0f;
            acc1[bb] = (kh == 0) ? 0.0f : xc[bb];
        }

        if (t + 1 < TT) {
            const float* xn = xp + ((size_t)(t + 1) * BB + b0) * GG + xrow;
#pragma unroll
            for (int bb = 0; bb < 4; bb++) xc[bb] = xn[bb * GG];
        }

#pragma unroll
        for (int k4 = 0; k4 < 16; k4++) {
            float4 w0 = *(const float4*)(w0p + 4 * k4);
            float4 w1 = w1r[k4];
            int k = k0 + 4 * k4;
#pragma unroll
            for (int bb = 0; bb < 4; bb++) {
                float4 hb = *(const float4*)&h_s[bb * HH + k];
                acc0[bb] += hb.x * w0.x + hb.y * w0.y + hb.z * w0.z + hb.w * w0.w;
                acc1[bb] += hb.x * w1.x + hb.y * w1.y + hb.z * w1.z + hb.w * w1.w;
            }
        }
        // partials: gp[(kh*4+bb)*512 + row]
#pragma unroll
        for (int bb = 0; bb < 4; bb++) {
            gp[(kh * 4 + bb) * 512 + t8]       = acc0[bb];
            gp[(kh * 4 + bb) * 512 + 256 + t8] = acc1[bb];
        }
        __syncthreads();

        // gate update: one cell per thread
        {
            int bb = tid >> 7, hh = tid & 127;
            const float* g0 = &gp[bb * 512];
            const float* g1 = &gp[(4 + bb) * 512];
            float gi = g0[hh]       + g1[hh];
            float gf = g0[128 + hh] + g1[128 + hh];
            float gc = g0[256 + hh] + g1[256 + hh];
            float go = g0[384 + hh] + g1[384 + hh];
            float cc = fsig(gf) * c_s[tid] + fsig(gi) * ftanh(gc);
            float h  = fsig(go) * ftanh(cc);
            c_s[tid] = cc;
            h_s[tid] = h;
            size_t oi = ((size_t)t * BB + b0 + bb) * HH + hh;
            __nv_bfloat16 hb16 = __float2bfloat16(h);
            hhi[oi] = hb16;
            hlo[oi] = __float2bfloat16(h - __bfloat162float(hb16));
            if (houtf) houtf[oi] = h;
        }
        __syncthreads();
    }
}

// ---------------- attn[n] = sum_h tanh(tmp[n,h]) * v[h] ----------------
__global__ void __launch_bounds__(256) attn_kernel(const float* __restrict__ tmp,
                                                   const float* __restrict__ v) {
    int warp = threadIdx.x >> 5, lane = threadIdx.x & 31;
    int n = blockIdx.x * 8 + warp;
    const float* row = tmp + (size_t)n * HH;
    float s = 0.0f;
#pragma unroll
    for (int j = lane; j < HH; j += 32) s += ftanh(row[j]) * v[j];
#pragma unroll
    for (int o = 16; o; o >>= 1) s += __shfl_xor_sync(0xffffffffu, s, o);
    if (lane == 0) g_attn[n] = s;
}

// ---------------- softmax + pool ----------------
__global__ void __launch_bounds__(128) pool_kernel() {
    int b = blockIdx.x;
    int tid = threadIdx.x;
    __shared__ float wt[TT];
    __shared__ float red[128];
    float a = (tid < TT) ? g_attn[tid * BB + b] : -1e30f;
    red[tid] = a;
    __syncthreads();
    for (int s = 64; s; s >>= 1) {
        if (tid < s) red[tid] = fmaxf(red[tid], red[tid + s]);
        __syncthreads();
    }
    float mx = red[0];
    __syncthreads();
    float e = (tid < TT) ? __expf(a - mx) : 0.0f;
    red[tid] = e;
    __syncthreads();
    for (int s = 64; s; s >>= 1) {
        if (tid < s) red[tid] += red[tid + s];
        __syncthreads();
    }
    float inv = __fdividef(1.0f, red[0]);
    if (tid < TT) wt[tid] = e * inv;
    __syncthreads();
    float acc = 0.0f;
#pragma unroll 4
    for (int t = 0; t < TT; t++)
        acc += wt[t] * g_h2[((size_t)t * BB + b) * HH + tid];
    g_pooled[b * HH + tid] = acc;
}

// ---------------- head ----------------
__global__ void __launch_bounds__(64) head_kernel(const float* __restrict__ W1,
                                                  const float* __restrict__ b1,
                                                  const float* __restrict__ W2,
                                                  const float* __restrict__ b2,
                                                  float* __restrict__ out) {
    int b = blockIdx.x;
    int tid = threadIdx.x;
    __shared__ float p[HH];
    __shared__ float hdn[64];
    for (int l = tid; l < HH; l += 64) p[l] = g_pooled[b * HH + l];
    __syncthreads();
    float acc = b1[tid];
#pragma unroll 8
    for (int k = 0; k < HH; k++) acc += p[k] * W1[tid * HH + k];
    hdn[tid] = acc;
    __syncthreads();
    if (tid < NC) {
        float o = b2[tid];
#pragma unroll
        for (int k = 0; k < 64; k++) o += hdn[k] * W2[tid * 64 + k];
        out[b * NC + tid] = o;
    }
}

// ---------------- host ----------------
extern "C" void kernel_launch(void* const* d_in, const int* in_sizes, int n_in,
                              void* d_out, int out_size) {
    const float* x      = (const float*)d_in[0];
    const float* conv_w = (const float*)d_in[1];
    const float* conv_b = (const float*)d_in[2];
    const float* Wih0   = (const float*)d_in[3];
    const float* Whh0   = (const float*)d_in[4];
    const float* bih0   = (const float*)d_in[5];
    const float* bhh0   = (const float*)d_in[6];
    const float* Wih1   = (const float*)d_in[7];
    const float* Whh1   = (const float*)d_in[8];
    const float* bih1   = (const float*)d_in[9];
    const float* bhh1   = (const float*)d_in[10];
    const float* W_att  = (const float*)d_in[11];
    const float* b_att  = (const float*)d_in[12];
    const float* v_att  = (const float*)d_in[13];
    const float* W1     = (const float*)d_in[14];
    const float* b1     = (const float*)d_in[15];
    const float* W2     = (const float*)d_in[16];
    const float* b2     = (const float*)d_in[17];
    float* out = (float*)d_out;

    float *xp_p, *h2_p, *wattT_p;
    __nv_bfloat16 *Ahi_p, *Alo_p, *W0hi_p, *W0lo_p, *W1hi_p, *W1lo_p, *Wahi_p, *Walo_p;
    cudaGetSymbolAddress((void**)&xp_p,    g_xp);
    cudaGetSymbolAddress((void**)&h2_p,    g_h2);
    cudaGetSymbolAddress((void**)&wattT_p, g_wattT);
    cudaGetSymbolAddress((void**)&Ahi_p,  g_Ahi);
    cudaGetSymbolAddress((void**)&Alo_p,  g_Alo);
    cudaGetSymbolAddress((void**)&W0hi_p, g_W0hi);
    cudaGetSymbolAddress((void**)&W0lo_p, g_W0lo);
    cudaGetSymbolAddress((void**)&W1hi_p, g_W1hi);
    cudaGetSymbolAddress((void**)&W1lo_p, g_W1lo);
    cudaGetSymbolAddress((void**)&Wahi_p, g_Wahi);
    cudaGetSymbolAddress((void**)&Walo_p, g_Walo);

    cudaFuncSetAttribute(conv_kernel, cudaFuncAttributeMaxDynamicSharedMemorySize,
                         812 * 40 * 4);
    cudaFuncSetAttribute(lstm_rec, cudaFuncAttributeMaxDynamicSharedMemorySize,
                         REC_SMEM);

    const int M = TT * BB;   // 51200

    // weight prep
    transpose_kernel<<<(HH * HH + 255) / 256, 256>>>(W_att, wattT_p, HH, HH);
    split_kernel<<<(GG * FF / 4 + 255) / 256, 256>>>(Wih0, W0hi_p, W0lo_p, GG * FF / 4);
    split_kernel<<<(GG * HH / 4 + 255) / 256, 256>>>(Wih1, W1hi_p, W1lo_p, GG * HH / 4);
    split_kernel<<<(HH * HH / 4 + 255) / 256, 256>>>(wattT_p, Wahi_p, Walo_p, HH * HH / 4);

    // conv -> Ahi/Alo (bf16 split fused)
    conv_kernel<<<BB, 256, 812 * 40 * 4>>>(x, conv_w, conv_b);

    // layer 0
    gemm_mma<<<dim3(GG / 128, M / 128), 256>>>(Ahi_p, Alo_p, W0hi_p, W0lo_p,
                                               bih0, bhh0, xp_p, M, GG, FF);
    lstm_rec<<<BB / 4, 512, REC_SMEM>>>(xp_p, Whh0, nullptr, Ahi_p, Alo_p);

    // layer 1 (A = h1 split, written by lstm_rec)
    gemm_mma<<<dim3(GG / 128, M / 128), 256>>>(Ahi_p, Alo_p, W1hi_p, W1lo_p,
                                               bih1, bhh1, xp_p, M, GG, HH);
    lstm_rec<<<BB / 4, 512, REC_SMEM>>>(xp_p, Whh1, h2_p, Ahi_p, Alo_p);

    // attention (A = h2 split)
    gemm_mma<<<dim3(HH / 128, M / 128), 256>>>(Ahi_p, Alo_p, Wahi_p, Walo_p,
                                               b_att, nullptr, xp_p, M, HH, HH);
    attn_kernel<<<(M) / 8, 256>>>(xp_p, v_att);
    pool_kernel<<<BB, 128>>>();
    head_kernel<<<BB, 64>>>(W1, b1, W2, b2, out);
}

// round 10
// speedup vs baseline: 1.9461x; 1.0025x over previous
#include <cuda_runtime.h>
#include <cuda_bf16.h>
#include <math.h>
#include <stdint.h>

// ---------------- problem constants ----------------
#define TT   100
#define BB   512
#define WW   18
#define CC   32
#define FF   576
#define HH   128
#define GG   512
#define NC   12

// ---------------- device scratch ----------------
__device__ float g_xp  [TT * BB * GG];
__device__ float g_h2  [TT * BB * HH];
__device__ float g_attn [TT * BB];
__device__ float g_pooled[BB * HH];
// bf16 split buffers
__device__ __nv_bfloat16 g_Ahi[TT * BB * FF];
__device__ __nv_bfloat16 g_Alo[TT * BB * FF];
__device__ __nv_bfloat16 g_W0hi[GG * FF], g_W0lo[GG * FF];
__device__ __nv_bfloat16 g_W1hi[GG * HH], g_W1lo[GG * HH];
__device__ __nv_bfloat16 g_Wahi[HH * HH], g_Walo[HH * HH];

// fast activations (EX2/RCP approx: rel err ~2e-7)
__device__ __forceinline__ float ftanh(float x) {
    float xc = fminf(fmaxf(x, -9.0f), 9.0f);
    float t = __expf(2.0f * xc);
    return __fdividef(t - 1.0f, t + 1.0f);
}
__device__ __forceinline__ float fsig(float x) {
    return __fdividef(1.0f, 1.0f + __expf(-x));
}

__device__ __forceinline__ uint32_t smem_u32(const void* p) {
    uint32_t a;
    asm("{ .reg .u64 t; cvta.to.shared.u64 t, %1; cvt.u32.u64 %0, t; }" : "=r"(a) : "l"(p));
    return a;
}
__device__ __forceinline__ void ldmat4(uint32_t* r, uint32_t addr) {
    asm volatile("ldmatrix.sync.aligned.m8n8.x4.shared.b16 {%0,%1,%2,%3}, [%4];"
                 : "=r"(r[0]), "=r"(r[1]), "=r"(r[2]), "=r"(r[3]) : "r"(addr));
}
__device__ __forceinline__ void mma16816(float* c, const uint32_t* a, const uint32_t* b) {
    asm volatile(
        "mma.sync.aligned.m16n8k16.row.col.f32.bf16.bf16.f32 "
        "{%0,%1,%2,%3}, {%4,%5,%6,%7}, {%8,%9}, {%0,%1,%2,%3};"
        : "+f"(c[0]), "+f"(c[1]), "+f"(c[2]), "+f"(c[3])
        : "r"(a[0]), "r"(a[1]), "r"(a[2]), "r"(a[3]), "r"(b[0]), "r"(b[1]));
}
__device__ __forceinline__ void split1(float v, __nv_bfloat16& h, __nv_bfloat16& l) {
    h = __float2bfloat16(v);
    l = __float2bfloat16(v - __bfloat162float(h));
}

// =====================================================================
// Fused weight prep: split Wih0, Wih1; transpose+split W_att. One launch.
// =====================================================================
#define N4_W0 (GG * FF / 4)
#define N4_W1 (GG * HH / 4)
#define N4_WA (HH * HH / 4)
__global__ void __launch_bounds__(256) prep_kernel(const float* __restrict__ Wih0,
                                                   const float* __restrict__ Wih1,
                                                   const float* __restrict__ W_att) {
    int i = blockIdx.x * 256 + threadIdx.x;
    if (i < N4_W0) {
        float4 v = ((const float4*)Wih0)[i];
        __nv_bfloat16 h0, h1, h2, h3, l0, l1, l2, l3;
        split1(v.x, h0, l0); split1(v.y, h1, l1);
        split1(v.z, h2, l2); split1(v.w, h3, l3);
        ((__nv_bfloat162*)g_W0hi)[2 * i]     = __nv_bfloat162(h0, h1);
        ((__nv_bfloat162*)g_W0hi)[2 * i + 1] = __nv_bfloat162(h2, h3);
        ((__nv_bfloat162*)g_W0lo)[2 * i]     = __nv_bfloat162(l0, l1);
        ((__nv_bfloat162*)g_W0lo)[2 * i + 1] = __nv_bfloat162(l2, l3);
    } else if (i < N4_W0 + N4_W1) {
        int j = i - N4_W0;
        float4 v = ((const float4*)Wih1)[j];
        __nv_bfloat16 h0, h1, h2, h3, l0, l1, l2, l3;
        split1(v.x, h0, l0); split1(v.y, h1, l1);
        split1(v.z, h2, l2); split1(v.w, h3, l3);
        ((__nv_bfloat162*)g_W1hi)[2 * j]     = __nv_bfloat162(h0, h1);
        ((__nv_bfloat162*)g_W1hi)[2 * j + 1] = __nv_bfloat162(h2, h3);
        ((__nv_bfloat162*)g_W1lo)[2 * j]     = __nv_bfloat162(l0, l1);
        ((__nv_bfloat162*)g_W1lo)[2 * j + 1] = __nv_bfloat162(l2, l3);
    } else if (i < N4_W0 + N4_W1 + N4_WA) {
        int j = (i - N4_W0 - N4_W1) * 4;
#pragma unroll
        for (int e = 0; e < 4; e++) {
            int idx = j + e;                    // output index: c*HH + r
            int c = idx >> 7, r = idx & 127;
            float v = W_att[r * HH + c];        // transpose
            __nv_bfloat16 h, l;
            split1(v, h, l);
            g_Wahi[idx] = h;
            g_Walo[idx] = l;
        }
    }
}

// =====================================================================
// Conv: one block per batch image; float4 patch reads; bf16 split out.
// =====================================================================
__global__ void __launch_bounds__(256, 1) conv_kernel(const float* __restrict__ x,
                                                      const float* __restrict__ cw,
                                                      const float* __restrict__ cb) {
    extern __shared__ float s_img[];
    int b = blockIdx.x;
    int tid = threadIdx.x;
    int wid = tid >> 5, lane = tid & 31;
    int c = lane;

    const float4* src = (const float4*)(x + (size_t)b * 812 * 40);
    float4* dst = (float4*)s_img;
    for (int i = tid; i < 812 * 10; i += 256) dst[i] = src[i];

    float wr[100];
#pragma unroll
    for (int i = 0; i < 100; i++) wr[i] = __ldg(&cw[c * 100 + i]);
    float bv = __ldg(&cb[c]);
    __syncthreads();

    for (int p = wid; p < 50; p += 8) {
        int base_row = 16 * p;
        float acc[2][18];
#pragma unroll
        for (int w = 0; w < 18; w++) { acc[0][w] = bv; acc[1][w] = bv; }
#pragma unroll
        for (int rr = 0; rr < 28; rr++) {
            const float4* prow4 = (const float4*)&s_img[(base_row + rr) * 40];
#pragma unroll
            for (int j4 = 0; j4 < 10; j4++) {
                float4 pj = prow4[j4];
                float pv4[4] = {pj.x, pj.y, pj.z, pj.w};
#pragma unroll
                for (int e = 0; e < 4; e++) {
                    int j = 4 * j4 + e;
                    float pv = pv4[e];
#pragma unroll
                    for (int kw = 0; kw < 5; kw++) {
                        int d = j - kw;
                        if (d >= 0 && (d & 1) == 0) {
                            int w = d >> 1;
                            if (w < 18) {
                                if (rr < 20) acc[0][w] += wr[rr * 5 + kw] * pv;
                                if (rr >= 8) acc[1][w] += wr[(rr - 8) * 5 + kw] * pv;
                            }
                        }
                    }
                }
            }
        }
#pragma unroll
        for (int ts = 0; ts < 2; ts++) {
            int t = 2 * p + ts;
            size_t base = ((size_t)t * BB + b) * FF + c;
#pragma unroll
            for (int w = 0; w < 18; w++) {
                float v = fmaxf(acc[ts][w], 0.0f);
                __nv_bfloat16 h, l;
                split1(v, h, l);
                g_Ahi[base + w * 32] = h;
                g_Alo[base + w * 32] = l;
            }
        }
    }
}

// =====================================================================
// bf16-split GEMM via mma.sync.m16n8k16 (round-8 design)
// =====================================================================
#define ASTR 40

__global__ void __launch_bounds__(256) gemm_mma(const __nv_bfloat16* __restrict__ Ahi,
                                                const __nv_bfloat16* __restrict__ Alo,
                                                const __nv_bfloat16* __restrict__ Bhi,
                                                const __nv_bfloat16* __restrict__ Blo,
                                                const float* __restrict__ bias0,
                                                const float* __restrict__ bias1,
                                                float* __restrict__ C,
                                                int M, int N, int K) {
    __shared__ __nv_bfloat16 sAhi[128 * ASTR], sAlo[128 * ASTR];
    __shared__ __nv_bfloat16 sBhi[128 * ASTR], sBlo[128 * ASTR];

    int tid = threadIdx.x;
    int warp = tid >> 5, lane = tid & 31;
    int wm = warp >> 2, wn = warp & 3;
    int bm = blockIdx.y * 128, bn = blockIdx.x * 128;

    int lrow0 = tid >> 1;
    int lseg0 = (tid & 1) * 2;
    const __nv_bfloat16* pAhi = Ahi + (size_t)(bm + lrow0) * K + lseg0 * 8;
    const __nv_bfloat16* pAlo = Alo + (size_t)(bm + lrow0) * K + lseg0 * 8;
    const __nv_bfloat16* pBhi = Bhi + (size_t)(bn + lrow0) * K + lseg0 * 8;
    const __nv_bfloat16* pBlo = Blo + (size_t)(bn + lrow0) * K + lseg0 * 8;

    float acc[4][4][4];
#pragma unroll
    for (int i = 0; i < 4; i++)
#pragma unroll
        for (int j = 0; j < 4; j++)
#pragma unroll
            for (int q = 0; q < 4; q++) acc[i][j][q] = 0.0f;

    uint32_t aAhi = smem_u32(sAhi), aAlo = smem_u32(sAlo);
    uint32_t aBhi = smem_u32(sBhi), aBlo = smem_u32(sBlo);

    uint32_t aRow = (uint32_t)(wm * 64 + (lane & 15));
    uint32_t aColHalf = (uint32_t)((lane >> 4) * 8);
    uint32_t g = (uint32_t)(lane >> 3);
    uint32_t bRow = (uint32_t)(wn * 32 + ((g >> 1) * 8) + (lane & 7));
    uint32_t bColHalf = (g & 1) * 8;

    uint4 ra0, ra1, rb0, rb1, rc0, rc1, rd0, rd1;
    ra0 = *(const uint4*)pAhi;       ra1 = *(const uint4*)(pAhi + 8);
    rb0 = *(const uint4*)pAlo;       rb1 = *(const uint4*)(pAlo + 8);
    rc0 = *(const uint4*)pBhi;       rc1 = *(const uint4*)(pBhi + 8);
    rd0 = *(const uint4*)pBlo;       rd1 = *(const uint4*)(pBlo + 8);

    int nchunks = K >> 5;
    for (int c0 = 0; c0 < nchunks; c0++) {
        {
            uint4* d;
            d = (uint4*)&sAhi[lrow0 * ASTR + lseg0 * 8]; d[0] = ra0; d[1] = ra1;
            d = (uint4*)&sAlo[lrow0 * ASTR + lseg0 * 8]; d[0] = rb0; d[1] = rb1;
            d = (uint4*)&sBhi[lrow0 * ASTR + lseg0 * 8]; d[0] = rc0; d[1] = rc1;
            d = (uint4*)&sBlo[lrow0 * ASTR + lseg0 * 8]; d[0] = rd0; d[1] = rd1;
        }
        __syncthreads();

        if (c0 + 1 < nchunks) {
            int kn = (c0 + 1) << 5;
            ra0 = *(const uint4*)(pAhi + kn);  ra1 = *(const uint4*)(pAhi + kn + 8);
            rb0 = *(const uint4*)(pAlo + kn);  rb1 = *(const uint4*)(pAlo + kn + 8);
            rc0 = *(const uint4*)(pBhi + kn);  rc1 = *(const uint4*)(pBhi + kn + 8);
            rd0 = *(const uint4*)(pBlo + kn);  rd1 = *(const uint4*)(pBlo + kn + 8);
        }

#pragma unroll
        for (int ko = 0; ko < 32; ko += 16) {
            uint32_t fahi[4][4], falo[4][4], fbhi[2][4], fblo[2][4];
#pragma unroll
            for (int mi = 0; mi < 4; mi++) {
                uint32_t off = ((aRow + mi * 16) * ASTR + ko + aColHalf) * 2;
                ldmat4(fahi[mi], aAhi + off);
                ldmat4(falo[mi], aAlo + off);
            }
#pragma unroll
            for (int np = 0; np < 2; np++) {
                uint32_t off = ((bRow + np * 16) * ASTR + ko + bColHalf) * 2;
                ldmat4(fbhi[np], aBhi + off);
                ldmat4(fblo[np], aBlo + off);
            }
#pragma unroll
            for (int mi = 0; mi < 4; mi++) {
#pragma unroll
                for (int nt = 0; nt < 4; nt++) {
                    int np = nt >> 1, hf = (nt & 1) * 2;
                    uint32_t bh[2] = { fbhi[np][hf], fbhi[np][hf + 1] };
                    uint32_t bl[2] = { fblo[np][hf], fblo[np][hf + 1] };
                    mma16816(acc[mi][nt], fahi[mi], bh);
                    mma16816(acc[mi][nt], falo[mi], bh);
                    mma16816(acc[mi][nt], fahi[mi], bl);
                }
            }
        }
        __syncthreads();
    }

#pragma unroll
    for (int nt = 0; nt < 4; nt++) {
        int col = bn + wn * 32 + nt * 8 + (lane & 3) * 2;
        float bv0 = 0.0f, bv1 = 0.0f;
        if (bias0) { bv0 += bias0[col]; bv1 += bias0[col + 1]; }
        if (bias1) { bv0 += bias1[col]; bv1 += bias1[col + 1]; }
#pragma unroll
        for (int mi = 0; mi < 4; mi++) {
            int row = bm + wm * 64 + mi * 16 + (lane >> 2);
            float2 v0 = make_float2(acc[mi][nt][0] + bv0, acc[mi][nt][1] + bv1);
            float2 v1 = make_float2(acc[mi][nt][2] + bv0, acc[mi][nt][3] + bv1);
            *(float2*)&C[(size_t)row * N + col] = v0;
            *(float2*)&C[(size_t)(row + 8) * N + col] = v1;
        }
    }
}

// =====================================================================
// Attention GEMM with fused tanh-dot epilogue: writes g_attn directly.
// N = 128 (one column tile), grid = (1, M/128). K = HH = 128.
// =====================================================================
__global__ void __launch_bounds__(256) gemm_att(const __nv_bfloat16* __restrict__ Ahi,
                                                const __nv_bfloat16* __restrict__ Alo,
                                                const __nv_bfloat16* __restrict__ Bhi,
                                                const __nv_bfloat16* __restrict__ Blo,
                                                const float* __restrict__ bias0,
                                                const float* __restrict__ vatt,
                                                int M, int K) {
    __shared__ __nv_bfloat16 sAhi[128 * ASTR], sAlo[128 * ASTR];
    __shared__ __nv_bfloat16 sBhi[128 * ASTR], sBlo[128 * ASTR];
    __shared__ float sred[128 * 4];

    int tid = threadIdx.x;
    int warp = tid >> 5, lane = tid & 31;
    int wm = warp >> 2, wn = warp & 3;
    int bm = blockIdx.y * 128;

    int lrow0 = tid >> 1;
    int lseg0 = (tid & 1) * 2;
    const __nv_bfloat16* pAhi = Ahi + (size_t)(bm + lrow0) * K + lseg0 * 8;
    const __nv_bfloat16* pAlo = Alo + (size_t)(bm + lrow0) * K + lseg0 * 8;
    const __nv_bfloat16* pBhi = Bhi + (size_t)lrow0 * K + lseg0 * 8;
    const __nv_bfloat16* pBlo = Blo + (size_t)lrow0 * K + lseg0 * 8;

    float acc[4][4][4];
#pragma unroll
    for (int i = 0; i < 4; i++)
#pragma unroll
        for (int j = 0; j < 4; j++)
#pragma unroll
            for (int q = 0; q < 4; q++) acc[i][j][q] = 0.0f;

    uint32_t aAhi = smem_u32(sAhi), aAlo = smem_u32(sAlo);
    uint32_t aBhi = smem_u32(sBhi), aBlo = smem_u32(sBlo);

    uint32_t aRow = (uint32_t)(wm * 64 + (lane & 15));
    uint32_t aColHalf = (uint32_t)((lane >> 4) * 8);
    uint32_t g = (uint32_t)(lane >> 3);
    uint32_t bRow = (uint32_t)(wn * 32 + ((g >> 1) * 8) + (lane & 7));
    uint32_t bColHalf = (g & 1) * 8;

    uint4 ra0, ra1, rb0, rb1, rc0, rc1, rd0, rd1;
    ra0 = *(const uint4*)pAhi;       ra1 = *(const uint4*)(pAhi + 8);
    rb0 = *(const uint4*)pAlo;       rb1 = *(const uint4*)(pAlo + 8);
    rc0 = *(const uint4*)pBhi;       rc1 = *(const uint4*)(pBhi + 8);
    rd0 = *(const uint4*)pBlo;       rd1 = *(const uint4*)(pBlo + 8);

    int nchunks = K >> 5;
    for (int c0 = 0; c0 < nchunks; c0++) {
        {
            uint4* d;
            d = (uint4*)&sAhi[lrow0 * ASTR + lseg0 * 8]; d[0] = ra0; d[1] = ra1;
            d = (uint4*)&sAlo[lrow0 * ASTR + lseg0 * 8]; d[0] = rb0; d[1] = rb1;
            d = (uint4*)&sBhi[lrow0 * ASTR + lseg0 * 8]; d[0] = rc0; d[1] = rc1;
            d = (uint4*)&sBlo[lrow0 * ASTR + lseg0 * 8]; d[0] = rd0; d[1] = rd1;
        }
        __syncthreads();

        if (c0 + 1 < nchunks) {
            int kn = (c0 + 1) << 5;
            ra0 = *(const uint4*)(pAhi + kn);  ra1 = *(const uint4*)(pAhi + kn + 8);
            rb0 = *(const uint4*)(pAlo + kn);  rb1 = *(const uint4*)(pAlo + kn + 8);
            rc0 = *(const uint4*)(pBhi + kn);  rc1 = *(const uint4*)(pBhi + kn + 8);
            rd0 = *(const uint4*)(pBlo + kn);  rd1 = *(const uint4*)(pBlo + kn + 8);
        }

#pragma unroll
        for (int ko = 0; ko < 32; ko += 16) {
            uint32_t fahi[4][4], falo[4][4], fbhi[2][4], fblo[2][4];
#pragma unroll
            for (int mi = 0; mi < 4; mi++) {
                uint32_t off = ((aRow + mi * 16) * ASTR + ko + aColHalf) * 2;
                ldmat4(fahi[mi], aAhi + off);
                ldmat4(falo[mi], aAlo + off);
            }
#pragma unroll
            for (int np = 0; np < 2; np++) {
                uint32_t off = ((bRow + np * 16) * ASTR + ko + bColHalf) * 2;
                ldmat4(fbhi[np], aBhi + off);
                ldmat4(fblo[np], aBlo + off);
            }
#pragma unroll
            for (int mi = 0; mi < 4; mi++) {
#pragma unroll
                for (int nt = 0; nt < 4; nt++) {
                    int np = nt >> 1, hf = (nt & 1) * 2;
                    uint32_t bh[2] = { fbhi[np][hf], fbhi[np][hf + 1] };
                    uint32_t bl[2] = { fblo[np][hf], fblo[np][hf + 1] };
                    mma16816(acc[mi][nt], fahi[mi], bh);
                    mma16816(acc[mi][nt], falo[mi], bh);
                    mma16816(acc[mi][nt], fahi[mi], bl);
                }
            }
        }
        __syncthreads();
    }

    // fused attention epilogue: attn[row] = sum_col tanh(acc + b_att) * v_att
    float rsum[4][2];
#pragma unroll
    for (int mi = 0; mi < 4; mi++) { rsum[mi][0] = 0.0f; rsum[mi][1] = 0.0f; }
#pragma unroll
    for (int nt = 0; nt < 4; nt++) {
        int col = wn * 32 + nt * 8 + (lane & 3) * 2;
        float b0v = bias0[col], b1v = bias0[col + 1];
        float v0 = vatt[col], v1 = vatt[col + 1];
#pragma unroll
        for (int mi = 0; mi < 4; mi++) {
            rsum[mi][0] += ftanh(acc[mi][nt][0] + b0v) * v0
                         + ftanh(acc[mi][nt][1] + b1v) * v1;
            rsum[mi][1] += ftanh(acc[mi][nt][2] + b0v) * v0
                         + ftanh(acc[mi][nt][3] + b1v) * v1;
        }
    }
#pragma unroll
    for (int off = 1; off <= 2; off <<= 1) {
#pragma unroll
        for (int mi = 0; mi < 4; mi++) {
            rsum[mi][0] += __shfl_xor_sync(0xffffffffu, rsum[mi][0], off);
            rsum[mi][1] += __shfl_xor_sync(0xffffffffu, rsum[mi][1], off);
        }
    }
    if ((lane & 3) == 0) {
#pragma unroll
        for (int mi = 0; mi < 4; mi++) {
            int r0 = wm * 64 + mi * 16 + (lane >> 2);
            sred[r0 * 4 + wn] = rsum[mi][0];
            sred[(r0 + 8) * 4 + wn] = rsum[mi][1];
        }
    }
    __syncthreads();
    if (tid < 128) {
        g_attn[bm + tid] = sred[tid * 4] + sred[tid * 4 + 1] +
                           sred[tid * 4 + 2] + sred[tid * 4 + 3];
    }
}

// =====================================================================
// LSTM recurrence, 512 threads (round-9 design)
// =====================================================================
#define WPAD 132
#define REC_SMEM ((256 * WPAD + 512 + 512 + 4096) * 4)
__global__ void __launch_bounds__(512, 1) lstm_rec(const float* __restrict__ xp,
                                                   const float* __restrict__ Whh,
                                                   float* __restrict__ houtf,
                                                   __nv_bfloat16* __restrict__ hhi,
                                                   __nv_bfloat16* __restrict__ hlo) {
    extern __shared__ float sm[];
    float* w_s = sm;
    float* h_s = w_s + 256 * WPAD;
    float* c_s = h_s + 512;
    float* gp  = c_s + 512;
    int tid = threadIdx.x;
    int t8 = tid & 255, kh = tid >> 8;
    int k0 = kh * 64;
    int b0 = blockIdx.x * 4;

    float4 w1r[16];
    const float* wg = Whh + (size_t)(256 + t8) * HH + k0;
#pragma unroll
    for (int i = 0; i < 16; i++) w1r[i] = __ldg((const float4*)(wg + 4 * i));

    for (int l = tid; l < 256 * HH; l += 512) {
        int r = l >> 7, k = l & 127;
        w_s[r * WPAD + k] = Whh[r * HH + k];
    }
    if (tid < 512) { h_s[tid] = 0.0f; c_s[tid] = 0.0f; }
    __syncthreads();

    const float* w0p = &w_s[t8 * WPAD + k0];

    int xrow = t8 + kh * 256;
    float xc[4];
    {
        const float* xpt = xp + (size_t)b0 * GG + xrow;
#pragma unroll
        for (int bb = 0; bb < 4; bb++) xc[bb] = xpt[bb * GG];
    }

    for (int t = 0; t < TT; t++) {
        float acc0[4], acc1[4];
#pragma unroll
        for (int bb = 0; bb < 4; bb++) {
            acc0[bb] = (kh == 0) ? xc[bb] : 0.0f;
            acc1[bb] = (kh == 0) ? 0.0f : xc[bb];
        }

        if (t + 1 < TT) {
            const float* xn = xp + ((size_t)(t + 1) * BB + b0) * GG + xrow;
#pragma unroll
            for (int bb = 0; bb < 4; bb++) xc[bb] = xn[bb * GG];
        }

#pragma unroll
        for (int k4 = 0; k4 < 16; k4++) {
            float4 w0 = *(const float4*)(w0p + 4 * k4);
            float4 w1 = w1r[k4];
            int k = k0 + 4 * k4;
#pragma unroll
            for (int bb = 0; bb < 4; bb++) {
                float4 hb = *(const float4*)&h_s[bb * HH + k];
                acc0[bb] += hb.x * w0.x + hb.y * w0.y + hb.z * w0.z + hb.w * w0.w;
                acc1[bb] += hb.x * w1.x + hb.y * w1.y + hb.z * w1.z + hb.w * w1.w;
            }
        }
#pragma unroll
        for (int bb = 0; bb < 4; bb++) {
            gp[(kh * 4 + bb) * 512 + t8]       = acc0[bb];
            gp[(kh * 4 + bb) * 512 + 256 + t8] = acc1[bb];
        }
        __syncthreads();

        {
            int bb = tid >> 7, hh = tid & 127;
            const float* g0 = &gp[bb * 512];
            const float* g1 = &gp[(4 + bb) * 512];
            float gi = g0[hh]       + g1[hh];
            float gf = g0[128 + hh] + g1[128 + hh];
            float gc = g0[256 + hh] + g1[256 + hh];
            float go = g0[384 + hh] + g1[384 + hh];
            float cc = fsig(gf) * c_s[tid] + fsig(gi) * ftanh(gc);
            float h  = fsig(go) * ftanh(cc);
            c_s[tid] = cc;
            h_s[tid] = h;
            size_t oi = ((size_t)t * BB + b0 + bb) * HH + hh;
            __nv_bfloat16 hb16 = __float2bfloat16(h);
            hhi[oi] = hb16;
            hlo[oi] = __float2bfloat16(h - __bfloat162float(hb16));
            if (houtf) houtf[oi] = h;
        }
        __syncthreads();
    }
}

// ---------------- softmax + pool ----------------
__global__ void __launch_bounds__(128) pool_kernel() {
    int b = blockIdx.x;
    int tid = threadIdx.x;
    __shared__ float wt[TT];
    __shared__ float red[128];
    float a = (tid < TT) ? g_attn[tid * BB + b] : -1e30f;
    red[tid] = a;
    __syncthreads();
    for (int s = 64; s; s >>= 1) {
        if (tid < s) red[tid] = fmaxf(red[tid], red[tid + s]);
        __syncthreads();
    }
    float mx = red[0];
    __syncthreads();
    float e = (tid < TT) ? __expf(a - mx) : 0.0f;
    red[tid] = e;
    __syncthreads();
    for (int s = 64; s; s >>= 1) {
        if (tid < s) red[tid] += red[tid + s];
        __syncthreads();
    }
    float inv = __fdividef(1.0f, red[0]);
    if (tid < TT) wt[tid] = e * inv;
    __syncthreads();
    float acc = 0.0f;
#pragma unroll 4
    for (int t = 0; t < TT; t++)
        acc += wt[t] * g_h2[((size_t)t * BB + b) * HH + tid];
    g_pooled[b * HH + tid] = acc;
}

// ---------------- head ----------------
__global__ void __launch_bounds__(64) head_kernel(const float* __restrict__ W1,
                                                  const float* __restrict__ b1,
                                                  const float* __restrict__ W2,
                                                  const float* __restrict__ b2,
                                                  float* __restrict__ out) {
    int b = blockIdx.x;
    int tid = threadIdx.x;
    __shared__ float p[HH];
    __shared__ float hdn[64];
    for (int l = tid; l < HH; l += 64) p[l] = g_pooled[b * HH + l];
    __syncthreads();
    float acc = b1[tid];
#pragma unroll 8
    for (int k = 0; k < HH; k++) acc += p[k] * W1[tid * HH + k];
    hdn[tid] = acc;
    __syncthreads();
    if (tid < NC) {
        float o = b2[tid];
#pragma unroll
        for (int k = 0; k < 64; k++) o += hdn[k] * W2[tid * 64 + k];
        out[b * NC + tid] = o;
    }
}

// ---------------- host ----------------
extern "C" void kernel_launch(void* const* d_in, const int* in_sizes, int n_in,
                              void* d_out, int out_size) {
    const float* x      = (const float*)d_in[0];
    const float* conv_w = (const float*)d_in[1];
    const float* conv_b = (const float*)d_in[2];
    const float* Wih0   = (const float*)d_in[3];
    const float* Whh0   = (const float*)d_in[4];
    const float* bih0   = (const float*)d_in[5];
    const float* bhh0   = (const float*)d_in[6];
    const float* Wih1   = (const float*)d_in[7];
    const float* Whh1   = (const float*)d_in[8];
    const float* bih1   = (const float*)d_in[9];
    const float* bhh1   = (const float*)d_in[10];
    const float* W_att  = (const float*)d_in[11];
    const float* b_att  = (const float*)d_in[12];
    const float* v_att  = (const float*)d_in[13];
    const float* W1     = (const float*)d_in[14];
    const float* b1     = (const float*)d_in[15];
    const float* W2     = (const float*)d_in[16];
    const float* b2     = (const float*)d_in[17];
    float* out = (float*)d_out;

    float *xp_p, *h2_p;
    __nv_bfloat16 *Ahi_p, *Alo_p, *W0hi_p, *W0lo_p, *W1hi_p, *W1lo_p, *Wahi_p, *Walo_p;
    cudaGetSymbolAddress((void**)&xp_p,    g_xp);
    cudaGetSymbolAddress((void**)&h2_p,    g_h2);
    cudaGetSymbolAddress((void**)&Ahi_p,  g_Ahi);
    cudaGetSymbolAddress((void**)&Alo_p,  g_Alo);
    cudaGetSymbolAddress((void**)&W0hi_p, g_W0hi);
    cudaGetSymbolAddress((void**)&W0lo_p, g_W0lo);
    cudaGetSymbolAddress((void**)&W1hi_p, g_W1hi);
    cudaGetSymbolAddress((void**)&W1lo_p, g_W1lo);
    cudaGetSymbolAddress((void**)&Wahi_p, g_Wahi);
    cudaGetSymbolAddress((void**)&Walo_p, g_Walo);

    cudaFuncSetAttribute(conv_kernel, cudaFuncAttributeMaxDynamicSharedMemorySize,
                         812 * 40 * 4);
    cudaFuncSetAttribute(lstm_rec, cudaFuncAttributeMaxDynamicSharedMemorySize,
                         REC_SMEM);

    const int M = TT * BB;   // 51200

    // fused weight prep (1 launch)
    prep_kernel<<<(N4_W0 + N4_W1 + N4_WA + 255) / 256, 256>>>(Wih0, Wih1, W_att);

    // conv -> Ahi/Alo (bf16 split fused)
    conv_kernel<<<BB, 256, 812 * 40 * 4>>>(x, conv_w, conv_b);

    // layer 0
    gemm_mma<<<dim3(GG / 128, M / 128), 256>>>(Ahi_p, Alo_p, W0hi_p, W0lo_p,
                                               bih0, bhh0, xp_p, M, GG, FF);
    lstm_rec<<<BB / 4, 512, REC_SMEM>>>(xp_p, Whh0, nullptr, Ahi_p, Alo_p);

    // layer 1
    gemm_mma<<<dim3(GG / 128, M / 128), 256>>>(Ahi_p, Alo_p, W1hi_p, W1lo_p,
                                               bih1, bhh1, xp_p, M, GG, HH);
    lstm_rec<<<BB / 4, 512, REC_SMEM>>>(xp_p, Whh1, h2_p, Ahi_p, Alo_p);

    // attention: GEMM + fused tanh-dot epilogue -> g_attn
    gemm_att<<<dim3(1, M / 128), 256>>>(Ahi_p, Alo_p, Wahi_p, Walo_p,
                                        b_att, v_att, M, HH);
    pool_kernel<<<BB, 128>>>();
    head_kernel<<<BB, 64>>>(W1, b1, W2, b2, out);
}

// round 11
// speedup vs baseline: 1.9719x; 1.0132x over previous
#include <cuda_runtime.h>
#include <cuda_bf16.h>
#include <math.h>
#include <stdint.h>

// ---------------- problem constants ----------------
#define TT   100
#define BB   512
#define WW   18
#define CC   32
#define FF   576
#define HH   128
#define GG   512
#define NC   12

// ---------------- device scratch ----------------
__device__ float g_xp  [TT * BB * GG];
__device__ float g_h2  [TT * BB * HH];
__device__ float g_attn [TT * BB];
__device__ float g_pooled[BB * HH];
__device__ __nv_bfloat16 g_Ahi[TT * BB * FF];
__device__ __nv_bfloat16 g_Alo[TT * BB * FF];
__device__ __nv_bfloat16 g_W0hi[GG * FF], g_W0lo[GG * FF];
__device__ __nv_bfloat16 g_W1hi[GG * HH], g_W1lo[GG * HH];
__device__ __nv_bfloat16 g_Wahi[HH * HH], g_Walo[HH * HH];

// fast activations (EX2/RCP approx)
__device__ __forceinline__ float ftanh(float x) {
    float xc = fminf(fmaxf(x, -9.0f), 9.0f);
    float t = __expf(2.0f * xc);
    return __fdividef(t - 1.0f, t + 1.0f);
}
__device__ __forceinline__ float fsig(float x) {
    return __fdividef(1.0f, 1.0f + __expf(-x));
}

// packed f32x2 helpers (PTX 8.6 baseline, sm_100+)
__device__ __forceinline__ void ffma2(unsigned long long& acc, unsigned long long a,
                                      unsigned long long b) {
    asm("fma.rn.f32x2 %0, %1, %2, %0;" : "+l"(acc) : "l"(a), "l"(b));
}
__device__ __forceinline__ unsigned long long packf2(float lo, float hi) {
    unsigned long long r;
    asm("mov.b64 %0, {%1,%2};" : "=l"(r) : "f"(lo), "f"(hi));
    return r;
}
__device__ __forceinline__ float2 unpackf2(unsigned long long v) {
    float2 r;
    asm("mov.b64 {%0,%1}, %2;" : "=f"(r.x), "=f"(r.y) : "l"(v));
    return r;
}

__device__ __forceinline__ uint32_t smem_u32(const void* p) {
    uint32_t a;
    asm("{ .reg .u64 t; cvta.to.shared.u64 t, %1; cvt.u32.u64 %0, t; }" : "=r"(a) : "l"(p));
    return a;
}
__device__ __forceinline__ void ldmat4(uint32_t* r, uint32_t addr) {
    asm volatile("ldmatrix.sync.aligned.m8n8.x4.shared.b16 {%0,%1,%2,%3}, [%4];"
                 : "=r"(r[0]), "=r"(r[1]), "=r"(r[2]), "=r"(r[3]) : "r"(addr));
}
__device__ __forceinline__ void mma16816(float* c, const uint32_t* a, const uint32_t* b) {
    asm volatile(
        "mma.sync.aligned.m16n8k16.row.col.f32.bf16.bf16.f32 "
        "{%0,%1,%2,%3}, {%4,%5,%6,%7}, {%8,%9}, {%0,%1,%2,%3};"
        : "+f"(c[0]), "+f"(c[1]), "+f"(c[2]), "+f"(c[3])
        : "r"(a[0]), "r"(a[1]), "r"(a[2]), "r"(a[3]), "r"(b[0]), "r"(b[1]));
}
__device__ __forceinline__ void split1(float v, __nv_bfloat16& h, __nv_bfloat16& l) {
    h = __float2bfloat16(v);
    l = __float2bfloat16(v - __bfloat162float(h));
}

// =====================================================================
// Weight prep (two launches so gemm0 lands at launch slot #4 for ncu)
// =====================================================================
#define N4_W0 (GG * FF / 4)
#define N4_W1 (GG * HH / 4)
#define N4_WA (HH * HH / 4)
__global__ void __launch_bounds__(256) prep_a(const float* __restrict__ Wih0) {
    int i = blockIdx.x * 256 + threadIdx.x;
    if (i >= N4_W0) return;
    float4 v = ((const float4*)Wih0)[i];
    __nv_bfloat16 h0, h1, h2, h3, l0, l1, l2, l3;
    split1(v.x, h0, l0); split1(v.y, h1, l1);
    split1(v.z, h2, l2); split1(v.w, h3, l3);
    ((__nv_bfloat162*)g_W0hi)[2 * i]     = __nv_bfloat162(h0, h1);
    ((__nv_bfloat162*)g_W0hi)[2 * i + 1] = __nv_bfloat162(h2, h3);
    ((__nv_bfloat162*)g_W0lo)[2 * i]     = __nv_bfloat162(l0, l1);
    ((__nv_bfloat162*)g_W0lo)[2 * i + 1] = __nv_bfloat162(l2, l3);
}
__global__ void __launch_bounds__(256) prep_b(const float* __restrict__ Wih1,
                                              const float* __restrict__ W_att) {
    int i = blockIdx.x * 256 + threadIdx.x;
    if (i < N4_W1) {
        float4 v = ((const float4*)Wih1)[i];
        __nv_bfloat16 h0, h1, h2, h3, l0, l1, l2, l3;
        split1(v.x, h0, l0); split1(v.y, h1, l1);
        split1(v.z, h2, l2); split1(v.w, h3, l3);
        ((__nv_bfloat162*)g_W1hi)[2 * i]     = __nv_bfloat162(h0, h1);
        ((__nv_bfloat162*)g_W1hi)[2 * i + 1] = __nv_bfloat162(h2, h3);
        ((__nv_bfloat162*)g_W1lo)[2 * i]     = __nv_bfloat162(l0, l1);
        ((__nv_bfloat162*)g_W1lo)[2 * i + 1] = __nv_bfloat162(l2, l3);
    } else if (i < N4_W1 + N4_WA) {
        int j = (i - N4_W1) * 4;
#pragma unroll
        for (int e = 0; e < 4; e++) {
            int idx = j + e;
            int c = idx >> 7, r = idx & 127;
            float v = W_att[r * HH + c];
            __nv_bfloat16 h, l;
            split1(v, h, l);
            g_Wahi[idx] = h;
            g_Walo[idx] = l;
        }
    }
}

// =====================================================================
// Conv (round-10 version)
// =====================================================================
__global__ void __launch_bounds__(256, 1) conv_kernel(const float* __restrict__ x,
                                                      const float* __restrict__ cw,
                                                      const float* __restrict__ cb) {
    extern __shared__ float s_img[];
    int b = blockIdx.x;
    int tid = threadIdx.x;
    int wid = tid >> 5, lane = tid & 31;
    int c = lane;

    const float4* src = (const float4*)(x + (size_t)b * 812 * 40);
    float4* dst = (float4*)s_img;
    for (int i = tid; i < 812 * 10; i += 256) dst[i] = src[i];

    float wr[100];
#pragma unroll
    for (int i = 0; i < 100; i++) wr[i] = __ldg(&cw[c * 100 + i]);
    float bv = __ldg(&cb[c]);
    __syncthreads();

    for (int p = wid; p < 50; p += 8) {
        int base_row = 16 * p;
        float acc[2][18];
#pragma unroll
        for (int w = 0; w < 18; w++) { acc[0][w] = bv; acc[1][w] = bv; }
#pragma unroll
        for (int rr = 0; rr < 28; rr++) {
            const float4* prow4 = (const float4*)&s_img[(base_row + rr) * 40];
#pragma unroll
            for (int j4 = 0; j4 < 10; j4++) {
                float4 pj = prow4[j4];
                float pv4[4] = {pj.x, pj.y, pj.z, pj.w};
#pragma unroll
                for (int e = 0; e < 4; e++) {
                    int j = 4 * j4 + e;
                    float pv = pv4[e];
#pragma unroll
                    for (int kw = 0; kw < 5; kw++) {
                        int d = j - kw;
                        if (d >= 0 && (d & 1) == 0) {
                            int w = d >> 1;
                            if (w < 18) {
                                if (rr < 20) acc[0][w] += wr[rr * 5 + kw] * pv;
                                if (rr >= 8) acc[1][w] += wr[(rr - 8) * 5 + kw] * pv;
                            }
                        }
                    }
                }
            }
        }
#pragma unroll
        for (int ts = 0; ts < 2; ts++) {
            int t = 2 * p + ts;
            size_t base = ((size_t)t * BB + b) * FF + c;
#pragma unroll
            for (int w = 0; w < 18; w++) {
                float v = fmaxf(acc[ts][w], 0.0f);
                __nv_bfloat16 h, l;
                split1(v, h, l);
                g_Ahi[base + w * 32] = h;
                g_Alo[base + w * 32] = l;
            }
        }
    }
}

// =====================================================================
// bf16-split GEMM via mma.sync, DOUBLE-BUFFERED dynamic smem.
// =====================================================================
#define ASTR 40
#define GTILE (128 * ASTR * 2)      // bytes per tile (10240)
#define GBUF  (4 * GTILE)           // bytes per buffer set (40960)
#define GSMEM (2 * GBUF)            // 81920

__global__ void __launch_bounds__(256) gemm_mma(const __nv_bfloat16* __restrict__ Ahi,
                                                const __nv_bfloat16* __restrict__ Alo,
                                                const __nv_bfloat16* __restrict__ Bhi,
                                                const __nv_bfloat16* __restrict__ Blo,
                                                const float* __restrict__ bias0,
                                                const float* __restrict__ bias1,
                                                float* __restrict__ C,
                                                int M, int N, int K) {
    extern __shared__ char gsm[];
    int tid = threadIdx.x;
    int warp = tid >> 5, lane = tid & 31;
    int wm = warp >> 2, wn = warp & 3;
    int bm = blockIdx.y * 128, bn = blockIdx.x * 128;

    int lrow0 = tid >> 1;
    int lseg0 = (tid & 1) * 2;
    const __nv_bfloat16* pAhi = Ahi + (size_t)(bm + lrow0) * K + lseg0 * 8;
    const __nv_bfloat16* pAlo = Alo + (size_t)(bm + lrow0) * K + lseg0 * 8;
    const __nv_bfloat16* pBhi = Bhi + (size_t)(bn + lrow0) * K + lseg0 * 8;
    const __nv_bfloat16* pBlo = Blo + (size_t)(bn + lrow0) * K + lseg0 * 8;

    float acc[4][4][4];
#pragma unroll
    for (int i = 0; i < 4; i++)
#pragma unroll
        for (int j = 0; j < 4; j++)
#pragma unroll
            for (int q = 0; q < 4; q++) acc[i][j][q] = 0.0f;

    uint32_t sb = smem_u32(gsm);
    uint32_t stoff = (uint32_t)(lrow0 * ASTR + lseg0 * 8) * 2;

    uint32_t aRow = (uint32_t)(wm * 64 + (lane & 15));
    uint32_t aColHalf = (uint32_t)((lane >> 4) * 8);
    uint32_t g = (uint32_t)(lane >> 3);
    uint32_t bRow = (uint32_t)(wn * 32 + ((g >> 1) * 8) + (lane & 7));
    uint32_t bColHalf = (g & 1) * 8;

    uint4 ra0, ra1, rb0, rb1, rc0, rc1, rd0, rd1;
    ra0 = *(const uint4*)pAhi;       ra1 = *(const uint4*)(pAhi + 8);
    rb0 = *(const uint4*)pAlo;       rb1 = *(const uint4*)(pAlo + 8);
    rc0 = *(const uint4*)pBhi;       rc1 = *(const uint4*)(pBhi + 8);
    rd0 = *(const uint4*)pBlo;       rd1 = *(const uint4*)(pBlo + 8);

    // stage chunk 0 into buffer 0
    {
        char* b0 = gsm + stoff;
        *(uint4*)(b0 + 0 * GTILE) = ra0; *(uint4*)(b0 + 0 * GTILE + 16) = ra1;
        *(uint4*)(b0 + 1 * GTILE) = rb0; *(uint4*)(b0 + 1 * GTILE + 16) = rb1;
        *(uint4*)(b0 + 2 * GTILE) = rc0; *(uint4*)(b0 + 2 * GTILE + 16) = rc1;
        *(uint4*)(b0 + 3 * GTILE) = rd0; *(uint4*)(b0 + 3 * GTILE + 16) = rd1;
    }
    __syncthreads();

    int nchunks = K >> 5;
    uint32_t cur = 0;
    for (int c0 = 0; c0 < nchunks; c0++) {
        bool more = (c0 + 1) < nchunks;
        if (more) {
            int kn = (c0 + 1) << 5;
            ra0 = *(const uint4*)(pAhi + kn);  ra1 = *(const uint4*)(pAhi + kn + 8);
            rb0 = *(const uint4*)(pAlo + kn);  rb1 = *(const uint4*)(pAlo + kn + 8);
            rc0 = *(const uint4*)(pBhi + kn);  rc1 = *(const uint4*)(pBhi + kn + 8);
            rd0 = *(const uint4*)(pBlo + kn);  rd1 = *(const uint4*)(pBlo + kn + 8);
        }

        uint32_t base = sb + cur * GBUF;
#pragma unroll
        for (int ko = 0; ko < 32; ko += 16) {
            uint32_t fahi[4][4], falo[4][4], fbhi[2][4], fblo[2][4];
#pragma unroll
            for (int mi = 0; mi < 4; mi++) {
                uint32_t off = ((aRow + mi * 16) * ASTR + ko + aColHalf) * 2;
                ldmat4(fahi[mi], base + 0 * GTILE + off);
                ldmat4(falo[mi], base + 1 * GTILE + off);
            }
#pragma unroll
            for (int np = 0; np < 2; np++) {
                uint32_t off = ((bRow + np * 16) * ASTR + ko + bColHalf) * 2;
                ldmat4(fbhi[np], base + 2 * GTILE + off);
                ldmat4(fblo[np], base + 3 * GTILE + off);
            }
#pragma unroll
            for (int mi = 0; mi < 4; mi++) {
#pragma unroll
                for (int nt = 0; nt < 4; nt++) {
                    int np = nt >> 1, hf = (nt & 1) * 2;
                    uint32_t bh[2] = { fbhi[np][hf], fbhi[np][hf + 1] };
                    uint32_t bl[2] = { fblo[np][hf], fblo[np][hf + 1] };
                    mma16816(acc[mi][nt], fahi[mi], bh);
                    mma16816(acc[mi][nt], falo[mi], bh);
                    mma16816(acc[mi][nt], fahi[mi], bl);
                }
            }
        }

        if (more) {
            char* bn2 = gsm + (cur ^ 1u) * GBUF + stoff;
            *(uint4*)(bn2 + 0 * GTILE) = ra0; *(uint4*)(bn2 + 0 * GTILE + 16) = ra1;
            *(uint4*)(bn2 + 1 * GTILE) = rb0; *(uint4*)(bn2 + 1 * GTILE + 16) = rb1;
            *(uint4*)(bn2 + 2 * GTILE) = rc0; *(uint4*)(bn2 + 2 * GTILE + 16) = rc1;
            *(uint4*)(bn2 + 3 * GTILE) = rd0; *(uint4*)(bn2 + 3 * GTILE + 16) = rd1;
        }
        __syncthreads();
        cur ^= 1u;
    }

#pragma unroll
    for (int nt = 0; nt < 4; nt++) {
        int col = bn + wn * 32 + nt * 8 + (lane & 3) * 2;
        float bv0 = 0.0f, bv1 = 0.0f;
        if (bias0) { bv0 += bias0[col]; bv1 += bias0[col + 1]; }
        if (bias1) { bv0 += bias1[col]; bv1 += bias1[col + 1]; }
#pragma unroll
        for (int mi = 0; mi < 4; mi++) {
            int row = bm + wm * 64 + mi * 16 + (lane >> 2);
            float2 v0 = make_float2(acc[mi][nt][0] + bv0, acc[mi][nt][1] + bv1);
            float2 v1 = make_float2(acc[mi][nt][2] + bv0, acc[mi][nt][3] + bv1);
            *(float2*)&C[(size_t)row * N + col] = v0;
            *(float2*)&C[(size_t)(row + 8) * N + col] = v1;
        }
    }
}

// =====================================================================
// Attention GEMM + fused tanh-dot epilogue (round-10, static smem)
// =====================================================================
__global__ void __launch_bounds__(256) gemm_att(const __nv_bfloat16* __restrict__ Ahi,
                                                const __nv_bfloat16* __restrict__ Alo,
                                                const __nv_bfloat16* __restrict__ Bhi,
                                                const __nv_bfloat16* __restrict__ Blo,
                                                const float* __restrict__ bias0,
                                                const float* __restrict__ vatt,
                                                int M, int K) {
    __shared__ __nv_bfloat16 sAhi[128 * ASTR], sAlo[128 * ASTR];
    __shared__ __nv_bfloat16 sBhi[128 * ASTR], sBlo[128 * ASTR];
    __shared__ float sred[128 * 4];

    int tid = threadIdx.x;
    int warp = tid >> 5, lane = tid & 31;
    int wm = warp >> 2, wn = warp & 3;
    int bm = blockIdx.y * 128;

    int lrow0 = tid >> 1;
    int lseg0 = (tid & 1) * 2;
    const __nv_bfloat16* pAhi = Ahi + (size_t)(bm + lrow0) * K + lseg0 * 8;
    const __nv_bfloat16* pAlo = Alo + (size_t)(bm + lrow0) * K + lseg0 * 8;
    const __nv_bfloat16* pBhi = Bhi + (size_t)lrow0 * K + lseg0 * 8;
    const __nv_bfloat16* pBlo = Blo + (size_t)lrow0 * K + lseg0 * 8;

    float acc[4][4][4];
#pragma unroll
    for (int i = 0; i < 4; i++)
#pragma unroll
        for (int j = 0; j < 4; j++)
#pragma unroll
            for (int q = 0; q < 4; q++) acc[i][j][q] = 0.0f;

    uint32_t aAhi = smem_u32(sAhi), aAlo = smem_u32(sAlo);
    uint32_t aBhi = smem_u32(sBhi), aBlo = smem_u32(sBlo);

    uint32_t aRow = (uint32_t)(wm * 64 + (lane & 15));
    uint32_t aColHalf = (uint32_t)((lane >> 4) * 8);
    uint32_t g = (uint32_t)(lane >> 3);
    uint32_t bRow = (uint32_t)(wn * 32 + ((g >> 1) * 8) + (lane & 7));
    uint32_t bColHalf = (g & 1) * 8;

    uint4 ra0, ra1, rb0, rb1, rc0, rc1, rd0, rd1;
    ra0 = *(const uint4*)pAhi;       ra1 = *(const uint4*)(pAhi + 8);
    rb0 = *(const uint4*)pAlo;       rb1 = *(const uint4*)(pAlo + 8);
    rc0 = *(const uint4*)pBhi;       rc1 = *(const uint4*)(pBhi + 8);
    rd0 = *(const uint4*)pBlo;       rd1 = *(const uint4*)(pBlo + 8);

    int nchunks = K >> 5;
    for (int c0 = 0; c0 < nchunks; c0++) {
        {
            uint4* d;
            d = (uint4*)&sAhi[lrow0 * ASTR + lseg0 * 8]; d[0] = ra0; d[1] = ra1;
            d = (uint4*)&sAlo[lrow0 * ASTR + lseg0 * 8]; d[0] = rb0; d[1] = rb1;
            d = (uint4*)&sBhi[lrow0 * ASTR + lseg0 * 8]; d[0] = rc0; d[1] = rc1;
            d = (uint4*)&sBlo[lrow0 * ASTR + lseg0 * 8]; d[0] = rd0; d[1] = rd1;
        }
        __syncthreads();

        if (c0 + 1 < nchunks) {
            int kn = (c0 + 1) << 5;
            ra0 = *(const uint4*)(pAhi + kn);  ra1 = *(const uint4*)(pAhi + kn + 8);
            rb0 = *(const uint4*)(pAlo + kn);  rb1 = *(const uint4*)(pAlo + kn + 8);
            rc0 = *(const uint4*)(pBhi + kn);  rc1 = *(const uint4*)(pBhi + kn + 8);
            rd0 = *(const uint4*)(pBlo + kn);  rd1 = *(const uint4*)(pBlo + kn + 8);
        }

#pragma unroll
        for (int ko = 0; ko < 32; ko += 16) {
            uint32_t fahi[4][4], falo[4][4], fbhi[2][4], fblo[2][4];
#pragma unroll
            for (int mi = 0; mi < 4; mi++) {
                uint32_t off = ((aRow + mi * 16) * ASTR + ko + aColHalf) * 2;
                ldmat4(fahi[mi], aAhi + off);
                ldmat4(falo[mi], aAlo + off);
            }
#pragma unroll
            for (int np = 0; np < 2; np++) {
                uint32_t off = ((bRow + np * 16) * ASTR + ko + bColHalf) * 2;
                ldmat4(fbhi[np], aBhi + off);
                ldmat4(fblo[np], aBlo + off);
            }
#pragma unroll
            for (int mi = 0; mi < 4; mi++) {
#pragma unroll
                for (int nt = 0; nt < 4; nt++) {
                    int np = nt >> 1, hf = (nt & 1) * 2;
                    uint32_t bh[2] = { fbhi[np][hf], fbhi[np][hf + 1] };
                    uint32_t bl[2] = { fblo[np][hf], fblo[np][hf + 1] };
                    mma16816(acc[mi][nt], fahi[mi], bh);
                    mma16816(acc[mi][nt], falo[mi], bh);
                    mma16816(acc[mi][nt], fahi[mi], bl);
                }
            }
        }
        __syncthreads();
    }

    float rsum[4][2];
#pragma unroll
    for (int mi = 0; mi < 4; mi++) { rsum[mi][0] = 0.0f; rsum[mi][1] = 0.0f; }
#pragma unroll
    for (int nt = 0; nt < 4; nt++) {
        int col = wn * 32 + nt * 8 + (lane & 3) * 2;
        float b0v = bias0[col], b1v = bias0[col + 1];
        float v0 = vatt[col], v1 = vatt[col + 1];
#pragma unroll
        for (int mi = 0; mi < 4; mi++) {
            rsum[mi][0] += ftanh(acc[mi][nt][0] + b0v) * v0
                         + ftanh(acc[mi][nt][1] + b1v) * v1;
            rsum[mi][1] += ftanh(acc[mi][nt][2] + b0v) * v0
                         + ftanh(acc[mi][nt][3] + b1v) * v1;
        }
    }
#pragma unroll
    for (int off = 1; off <= 2; off <<= 1) {
#pragma unroll
        for (int mi = 0; mi < 4; mi++) {
            rsum[mi][0] += __shfl_xor_sync(0xffffffffu, rsum[mi][0], off);
            rsum[mi][1] += __shfl_xor_sync(0xffffffffu, rsum[mi][1], off);
        }
    }
    if ((lane & 3) == 0) {
#pragma unroll
        for (int mi = 0; mi < 4; mi++) {
            int r0 = wm * 64 + mi * 16 + (lane >> 2);
            sred[r0 * 4 + wn] = rsum[mi][0];
            sred[(r0 + 8) * 4 + wn] = rsum[mi][1];
        }
    }
    __syncthreads();
    if (tid < 128) {
        g_attn[bm + tid] = sred[tid * 4] + sred[tid * 4 + 1] +
                           sred[tid * 4 + 2] + sred[tid * 4 + 3];
    }
}

// =====================================================================
// LSTM recurrence, 512 threads, FFMA2 (f32x2) inner loop.
// Packing over k: even/odd-k partial sums per accumulator.
// =====================================================================
#define WPAD 132
#define REC_SMEM ((256 * WPAD + 512 + 512 + 4096) * 4)
__global__ void __launch_bounds__(512, 1) lstm_rec(const float* __restrict__ xp,
                                                   const float* __restrict__ Whh,
                                                   float* __restrict__ houtf,
                                                   __nv_bfloat16* __restrict__ hhi,
                                                   __nv_bfloat16* __restrict__ hlo) {
    extern __shared__ float sm[];
    float* w_s = sm;
    float* h_s = w_s + 256 * WPAD;
    float* c_s = h_s + 512;
    float* gp  = c_s + 512;
    int tid = threadIdx.x;
    int t8 = tid & 255, kh = tid >> 8;
    int k0 = kh * 64;
    int b0 = blockIdx.x * 4;

    // upper-row reg weights (row t8+256, 64-float k-slice) as f32x2 pairs
    ulonglong2 w1r[16];
    const float* wg = Whh + (size_t)(256 + t8) * HH + k0;
#pragma unroll
    for (int i = 0; i < 16; i++) w1r[i] = __ldg((const ulonglong2*)(wg + 4 * i));

    for (int l = tid; l < 256 * HH; l += 512) {
        int r = l >> 7, k = l & 127;
        w_s[r * WPAD + k] = Whh[r * HH + k];
    }
    if (tid < 512) { h_s[tid] = 0.0f; c_s[tid] = 0.0f; }
    __syncthreads();

    const float* w0p = &w_s[t8 * WPAD + k0];

    int xrow = t8 + kh * 256;
    float xc[4];
    {
        const float* xpt = xp + (size_t)b0 * GG + xrow;
#pragma unroll
        for (int bb = 0; bb < 4; bb++) xc[bb] = xpt[bb * GG];
    }

    for (int t = 0; t < TT; t++) {
        unsigned long long a0v[4], a1v[4];
#pragma unroll
        for (int bb = 0; bb < 4; bb++) {
            a0v[bb] = packf2((kh == 0) ? xc[bb] : 0.0f, 0.0f);
            a1v[bb] = packf2((kh == 0) ? 0.0f : xc[bb], 0.0f);
        }

        if (t + 1 < TT) {
            const float* xn = xp + ((size_t)(t + 1) * BB + b0) * GG + xrow;
#pragma unroll
            for (int bb = 0; bb < 4; bb++) xc[bb] = xn[bb * GG];
        }

#pragma unroll
        for (int k4 = 0; k4 < 16; k4++) {
            ulonglong2 w0 = *(const ulonglong2*)(w0p + 4 * k4);
            ulonglong2 w1 = w1r[k4];
            int k = k0 + 4 * k4;
#pragma unroll
            for (int bb = 0; bb < 4; bb++) {
                ulonglong2 hb = *(const ulonglong2*)&h_s[bb * HH + k];
                ffma2(a0v[bb], hb.x, w0.x);
                ffma2(a0v[bb], hb.y, w0.y);
                ffma2(a1v[bb], hb.x, w1.x);
                ffma2(a1v[bb], hb.y, w1.y);
            }
        }
#pragma unroll
        for (int bb = 0; bb < 4; bb++) {
            float2 s0 = unpackf2(a0v[bb]);
            float2 s1 = unpackf2(a1v[bb]);
            gp[(kh * 4 + bb) * 512 + t8]       = s0.x + s0.y;
            gp[(kh * 4 + bb) * 512 + 256 + t8] = s1.x + s1.y;
        }
        __syncthreads();

        {
            int bb = tid >> 7, hh = tid & 127;
            const float* g0 = &gp[bb * 512];
            const float* g1 = &gp[(4 + bb) * 512];
            float gi = g0[hh]       + g1[hh];
            float gf = g0[128 + hh] + g1[128 + hh];
            float gc = g0[256 + hh] + g1[256 + hh];
            float go = g0[384 + hh] + g1[384 + hh];
            float cc = fsig(gf) * c_s[tid] + fsig(gi) * ftanh(gc);
            float h  = fsig(go) * ftanh(cc);
            c_s[tid] = cc;
            h_s[tid] = h;
            size_t oi = ((size_t)t * BB + b0 + bb) * HH + hh;
            __nv_bfloat16 hb16 = __float2bfloat16(h);
            hhi[oi] = hb16;
            hlo[oi] = __float2bfloat16(h - __bfloat162float(hb16));
            if (houtf) houtf[oi] = h;
        }
        __syncthreads();
    }
}

// ---------------- softmax + pool ----------------
__global__ void __launch_bounds__(128) pool_kernel() {
    int b = blockIdx.x;
    int tid = threadIdx.x;
    __shared__ float wt[TT];
    __shared__ float red[128];
    float a = (tid < TT) ? g_attn[tid * BB + b] : -1e30f;
    red[tid] = a;
    __syncthreads();
    for (int s = 64; s; s >>= 1) {
        if (tid < s) red[tid] = fmaxf(red[tid], red[tid + s]);
        __syncthreads();
    }
    float mx = red[0];
    __syncthreads();
    float e = (tid < TT) ? __expf(a - mx) : 0.0f;
    red[tid] = e;
    __syncthreads();
    for (int s = 64; s; s >>= 1) {
        if (tid < s) red[tid] += red[tid + s];
        __syncthreads();
    }
    float inv = __fdividef(1.0f, red[0]);
    if (tid < TT) wt[tid] = e * inv;
    __syncthreads();
    float acc = 0.0f;
#pragma unroll 4
    for (int t = 0; t < TT; t++)
        acc += wt[t] * g_h2[((size_t)t * BB + b) * HH + tid];
    g_pooled[b * HH + tid] = acc;
}

// ---------------- head ----------------
__global__ void __launch_bounds__(64) head_kernel(const float* __restrict__ W1,
                                                  const float* __restrict__ b1,
                                                  const float* __restrict__ W2,
                                                  const float* __restrict__ b2,
                                                  float* __restrict__ out) {
    int b = blockIdx.x;
    int tid = threadIdx.x;
    __shared__ float p[HH];
    __shared__ float hdn[64];
    for (int l = tid; l < HH; l += 64) p[l] = g_pooled[b * HH + l];
    __syncthreads();
    float acc = b1[tid];
#pragma unroll 8
    for (int k = 0; k < HH; k++) acc += p[k] * W1[tid * HH + k];
    hdn[tid] = acc;
    __syncthreads();
    if (tid < NC) {
        float o = b2[tid];
#pragma unroll
        for (int k = 0; k < 64; k++) o += hdn[k] * W2[tid * 64 + k];
        out[b * NC + tid] = o;
    }
}

// ---------------- host ----------------
extern "C" void kernel_launch(void* const* d_in, const int* in_sizes, int n_in,
                              void* d_out, int out_size) {
    const float* x      = (const float*)d_in[0];
    const float* conv_w = (const float*)d_in[1];
    const float* conv_b = (const float*)d_in[2];
    const float* Wih0   = (const float*)d_in[3];
    const float* Whh0   = (const float*)d_in[4];
    const float* bih0   = (const float*)d_in[5];
    const float* bhh0   = (const float*)d_in[6];
    const float* Wih1   = (const float*)d_in[7];
    const float* Whh1   = (const float*)d_in[8];
    const float* bih1   = (const float*)d_in[9];
    const float* bhh1   = (const float*)d_in[10];
    const float* W_att  = (const float*)d_in[11];
    const float* b_att  = (const float*)d_in[12];
    const float* v_att  = (const float*)d_in[13];
    const float* W1     = (const float*)d_in[14];
    const float* b1     = (const float*)d_in[15];
    const float* W2     = (const float*)d_in[16];
    const float* b2     = (const float*)d_in[17];
    float* out = (float*)d_out;

    float *xp_p, *h2_p;
    __nv_bfloat16 *Ahi_p, *Alo_p, *W0hi_p, *W0lo_p, *W1hi_p, *W1lo_p, *Wahi_p, *Walo_p;
    cudaGetSymbolAddress((void**)&xp_p,    g_xp);
    cudaGetSymbolAddress((void**)&h2_p,    g_h2);
    cudaGetSymbolAddress((void**)&Ahi_p,  g_Ahi);
    cudaGetSymbolAddress((void**)&Alo_p,  g_Alo);
    cudaGetSymbolAddress((void**)&W0hi_p, g_W0hi);
    cudaGetSymbolAddress((void**)&W0lo_p, g_W0lo);
    cudaGetSymbolAddress((void**)&W1hi_p, g_W1hi);
    cudaGetSymbolAddress((void**)&W1lo_p, g_W1lo);
    cudaGetSymbolAddress((void**)&Wahi_p, g_Wahi);
    cudaGetSymbolAddress((void**)&Walo_p, g_Walo);

    cudaFuncSetAttribute(conv_kernel, cudaFuncAttributeMaxDynamicSharedMemorySize,
                         812 * 40 * 4);
    cudaFuncSetAttribute(lstm_rec, cudaFuncAttributeMaxDynamicSharedMemorySize,
                         REC_SMEM);
    cudaFuncSetAttribute(gemm_mma, cudaFuncAttributeMaxDynamicSharedMemorySize,
                         GSMEM);

    const int M = TT * BB;   // 51200

    // launches #1,#2: weight prep
    prep_a<<<(N4_W0 + 255) / 256, 256>>>(Wih0);
    prep_b<<<(N4_W1 + N4_WA + 255) / 256, 256>>>(Wih1, W_att);

    // launch #3: conv -> Ahi/Alo
    conv_kernel<<<BB, 256, 812 * 40 * 4>>>(x, conv_w, conv_b);

    // launch #4 (ncu capture slot): layer-0 GEMM
    gemm_mma<<<dim3(GG / 128, M / 128), 256, GSMEM>>>(Ahi_p, Alo_p, W0hi_p, W0lo_p,
                                                      bih0, bhh0, xp_p, M, GG, FF);
    lstm_rec<<<BB / 4, 512, REC_SMEM>>>(xp_p, Whh0, nullptr, Ahi_p, Alo_p);

    gemm_mma<<<dim3(GG / 128, M / 128), 256, GSMEM>>>(Ahi_p, Alo_p, W1hi_p, W1lo_p,
                                                      bih1, bhh1, xp_p, M, GG, HH);
    lstm_rec<<<BB / 4, 512, REC_SMEM>>>(xp_p, Whh1, h2_p, Ahi_p, Alo_p);

    gemm_att<<<dim3(1, M / 128), 256>>>(Ahi_p, Alo_p, Wahi_p, Walo_p,
                                        b_att, v_att, M, HH);
    pool_kernel<<<BB, 128>>>();
    head_kernel<<<BB, 64>>>(W1, b1, W2, b2, out);
}

// round 12
// speedup vs baseline: 2.1293x; 1.0799x over previous
#include <cuda_runtime.h>
#include <cuda_bf16.h>
#include <math.h>
#include <stdint.h>

// ---------------- problem constants ----------------
#define TT   100
#define BB   512
#define WW   18
#define CC   32
#define FF   576
#define HH   128
#define GG   512
#define NC   12

// ---------------- device scratch ----------------
__device__ float g_xp  [TT * BB * GG];
__device__ float g_h2  [TT * BB * HH];
__device__ float g_attn [TT * BB];
__device__ float g_pooled[BB * HH];
__device__ __nv_bfloat16 g_Ahi[TT * BB * FF];
__device__ __nv_bfloat16 g_W0hi[GG * FF], g_W0lo[GG * FF];
__device__ __nv_bfloat16 g_W1hi[GG * HH], g_W1lo[GG * HH];
__device__ __nv_bfloat16 g_Wahi[HH * HH], g_Walo[HH * HH];

// fast activations (EX2/RCP approx)
__device__ __forceinline__ float ftanh(float x) {
    float xc = fminf(fmaxf(x, -9.0f), 9.0f);
    float t = __expf(2.0f * xc);
    return __fdividef(t - 1.0f, t + 1.0f);
}
__device__ __forceinline__ float fsig(float x) {
    return __fdividef(1.0f, 1.0f + __expf(-x));
}

// packed f32x2 helpers
__device__ __forceinline__ void ffma2(unsigned long long& acc, unsigned long long a,
                                      unsigned long long b) {
    asm("fma.rn.f32x2 %0, %1, %2, %0;" : "+l"(acc) : "l"(a), "l"(b));
}
__device__ __forceinline__ unsigned long long packf2(float lo, float hi) {
    unsigned long long r;
    asm("mov.b64 %0, {%1,%2};" : "=l"(r) : "f"(lo), "f"(hi));
    return r;
}
__device__ __forceinline__ float2 unpackf2(unsigned long long v) {
    float2 r;
    asm("mov.b64 {%0,%1}, %2;" : "=f"(r.x), "=f"(r.y) : "l"(v));
    return r;
}

__device__ __forceinline__ uint32_t smem_u32(const void* p) {
    uint32_t a;
    asm("{ .reg .u64 t; cvta.to.shared.u64 t, %1; cvt.u32.u64 %0, t; }" : "=r"(a) : "l"(p));
    return a;
}
__device__ __forceinline__ void ldmat4(uint32_t* r, uint32_t addr) {
    asm volatile("ldmatrix.sync.aligned.m8n8.x4.shared.b16 {%0,%1,%2,%3}, [%4];"
                 : "=r"(r[0]), "=r"(r[1]), "=r"(r[2]), "=r"(r[3]) : "r"(addr));
}
__device__ __forceinline__ void mma16816(float* c, const uint32_t* a, const uint32_t* b) {
    asm volatile(
        "mma.sync.aligned.m16n8k16.row.col.f32.bf16.bf16.f32 "
        "{%0,%1,%2,%3}, {%4,%5,%6,%7}, {%8,%9}, {%0,%1,%2,%3};"
        : "+f"(c[0]), "+f"(c[1]), "+f"(c[2]), "+f"(c[3])
        : "r"(a[0]), "r"(a[1]), "r"(a[2]), "r"(a[3]), "r"(b[0]), "r"(b[1]));
}
__device__ __forceinline__ void split1(float v, __nv_bfloat16& h, __nv_bfloat16& l) {
    h = __float2bfloat16(v);
    l = __float2bfloat16(v - __bfloat162float(h));
}

// =====================================================================
// Weight prep: 3 launches (so conv lands at ncu slot #4)
// =====================================================================
#define N4_W0 (GG * FF / 4)
#define N4_W1 (GG * HH / 4)
#define N4_WA (HH * HH / 4)
__global__ void __launch_bounds__(256) prep_a(const float* __restrict__ Wih0) {
    int i = blockIdx.x * 256 + threadIdx.x;
    if (i >= N4_W0) return;
    float4 v = ((const float4*)Wih0)[i];
    __nv_bfloat16 h0, h1, h2, h3, l0, l1, l2, l3;
    split1(v.x, h0, l0); split1(v.y, h1, l1);
    split1(v.z, h2, l2); split1(v.w, h3, l3);
    ((__nv_bfloat162*)g_W0hi)[2 * i]     = __nv_bfloat162(h0, h1);
    ((__nv_bfloat162*)g_W0hi)[2 * i + 1] = __nv_bfloat162(h2, h3);
    ((__nv_bfloat162*)g_W0lo)[2 * i]     = __nv_bfloat162(l0, l1);
    ((__nv_bfloat162*)g_W0lo)[2 * i + 1] = __nv_bfloat162(l2, l3);
}
__global__ void __launch_bounds__(256) prep_b(const float* __restrict__ Wih1) {
    int i = blockIdx.x * 256 + threadIdx.x;
    if (i >= N4_W1) return;
    float4 v = ((const float4*)Wih1)[i];
    __nv_bfloat16 h0, h1, h2, h3, l0, l1, l2, l3;
    split1(v.x, h0, l0); split1(v.y, h1, l1);
    split1(v.z, h2, l2); split1(v.w, h3, l3);
    ((__nv_bfloat162*)g_W1hi)[2 * i]     = __nv_bfloat162(h0, h1);
    ((__nv_bfloat162*)g_W1hi)[2 * i + 1] = __nv_bfloat162(h2, h3);
    ((__nv_bfloat162*)g_W1lo)[2 * i]     = __nv_bfloat162(l0, l1);
    ((__nv_bfloat162*)g_W1lo)[2 * i + 1] = __nv_bfloat162(l2, l3);
}
__global__ void __launch_bounds__(256) prep_c(const float* __restrict__ W_att) {
    int i = blockIdx.x * 256 + threadIdx.x;
    if (i >= N4_WA) return;
    int j = i * 4;
#pragma unroll
    for (int e = 0; e < 4; e++) {
        int idx = j + e;
        int c = idx >> 7, r = idx & 127;
        float v = W_att[r * HH + c];
        __nv_bfloat16 h, l;
        split1(v, h, l);
        g_Wahi[idx] = h;
        g_Walo[idx] = l;
    }
}

// =====================================================================
// Conv: one block per batch image; writes bf16 hi only.
// =====================================================================
__global__ void __launch_bounds__(256, 1) conv_kernel(const float* __restrict__ x,
                                                      const float* __restrict__ cw,
                                                      const float* __restrict__ cb) {
    extern __shared__ float s_img[];
    int b = blockIdx.x;
    int tid = threadIdx.x;
    int wid = tid >> 5, lane = tid & 31;
    int c = lane;

    const float4* src = (const float4*)(x + (size_t)b * 812 * 40);
    float4* dst = (float4*)s_img;
    for (int i = tid; i < 812 * 10; i += 256) dst[i] = src[i];

    float wr[100];
#pragma unroll
    for (int i = 0; i < 100; i++) wr[i] = __ldg(&cw[c * 100 + i]);
    float bv = __ldg(&cb[c]);
    __syncthreads();

    for (int p = wid; p < 50; p += 8) {
        int base_row = 16 * p;
        float acc[2][18];
#pragma unroll
        for (int w = 0; w < 18; w++) { acc[0][w] = bv; acc[1][w] = bv; }
#pragma unroll
        for (int rr = 0; rr < 28; rr++) {
            const float4* prow4 = (const float4*)&s_img[(base_row + rr) * 40];
#pragma unroll
            for (int j4 = 0; j4 < 10; j4++) {
                float4 pj = prow4[j4];
                float pv4[4] = {pj.x, pj.y, pj.z, pj.w};
#pragma unroll
                for (int e = 0; e < 4; e++) {
                    int j = 4 * j4 + e;
                    float pv = pv4[e];
#pragma unroll
                    for (int kw = 0; kw < 5; kw++) {
                        int d = j - kw;
                        if (d >= 0 && (d & 1) == 0) {
                            int w = d >> 1;
                            if (w < 18) {
                                if (rr < 20) acc[0][w] += wr[rr * 5 + kw] * pv;
                                if (rr >= 8) acc[1][w] += wr[(rr - 8) * 5 + kw] * pv;
                            }
                        }
                    }
                }
            }
        }
#pragma unroll
        for (int ts = 0; ts < 2; ts++) {
            int t = 2 * p + ts;
            size_t base = ((size_t)t * BB + b) * FF + c;
#pragma unroll
            for (int w = 0; w < 18; w++)
                g_Ahi[base + w * 32] = __float2bfloat16(fmaxf(acc[ts][w], 0.0f));
        }
    }
}

// =====================================================================
// 2-term GEMM: C = Ahi@(Bhi+Blo)^T + bias. mma.sync, double-buffered.
// Per ko: 8 LDSM.x4 (A 4, Bhi 2, Blo 2), 32 HMMA.
// =====================================================================
#define ASTR 40
#define GTILE (128 * ASTR * 2)      // 10240 bytes per tile
#define GBUF  (3 * GTILE)           // A, Bhi, Blo
#define GSMEM (2 * GBUF)            // 61440

__global__ void __launch_bounds__(256) gemm_mma(const __nv_bfloat16* __restrict__ Ahi,
                                                const __nv_bfloat16* __restrict__ Bhi,
                                                const __nv_bfloat16* __restrict__ Blo,
                                                const float* __restrict__ bias0,
                                                const float* __restrict__ bias1,
                                                float* __restrict__ C,
                                                int M, int N, int K) {
    extern __shared__ char gsm[];
    int tid = threadIdx.x;
    int warp = tid >> 5, lane = tid & 31;
    int wm = warp >> 2, wn = warp & 3;
    int bm = blockIdx.y * 128, bn = blockIdx.x * 128;

    int lrow0 = tid >> 1;
    int lseg0 = (tid & 1) * 2;
    const __nv_bfloat16* pAhi = Ahi + (size_t)(bm + lrow0) * K + lseg0 * 8;
    const __nv_bfloat16* pBhi = Bhi + (size_t)(bn + lrow0) * K + lseg0 * 8;
    const __nv_bfloat16* pBlo = Blo + (size_t)(bn + lrow0) * K + lseg0 * 8;

    float acc[4][4][4];
#pragma unroll
    for (int i = 0; i < 4; i++)
#pragma unroll
        for (int j = 0; j < 4; j++)
#pragma unroll
            for (int q = 0; q < 4; q++) acc[i][j][q] = 0.0f;

    uint32_t sb = smem_u32(gsm);
    uint32_t stoff = (uint32_t)(lrow0 * ASTR + lseg0 * 8) * 2;

    uint32_t aRow = (uint32_t)(wm * 64 + (lane & 15));
    uint32_t aColHalf = (uint32_t)((lane >> 4) * 8);
    uint32_t g = (uint32_t)(lane >> 3);
    uint32_t bRow = (uint32_t)(wn * 32 + ((g >> 1) * 8) + (lane & 7));
    uint32_t bColHalf = (g & 1) * 8;

    uint4 ra0, ra1, rc0, rc1, rd0, rd1;
    ra0 = *(const uint4*)pAhi;       ra1 = *(const uint4*)(pAhi + 8);
    rc0 = *(const uint4*)pBhi;       rc1 = *(const uint4*)(pBhi + 8);
    rd0 = *(const uint4*)pBlo;       rd1 = *(const uint4*)(pBlo + 8);

    {
        char* b0 = gsm + stoff;
        *(uint4*)(b0 + 0 * GTILE) = ra0; *(uint4*)(b0 + 0 * GTILE + 16) = ra1;
        *(uint4*)(b0 + 1 * GTILE) = rc0; *(uint4*)(b0 + 1 * GTILE + 16) = rc1;
        *(uint4*)(b0 + 2 * GTILE) = rd0; *(uint4*)(b0 + 2 * GTILE + 16) = rd1;
    }
    __syncthreads();

    int nchunks = K >> 5;
    uint32_t cur = 0;
    for (int c0 = 0; c0 < nchunks; c0++) {
        bool more = (c0 + 1) < nchunks;
        if (more) {
            int kn = (c0 + 1) << 5;
            ra0 = *(const uint4*)(pAhi + kn);  ra1 = *(const uint4*)(pAhi + kn + 8);
            rc0 = *(const uint4*)(pBhi + kn);  rc1 = *(const uint4*)(pBhi + kn + 8);
            rd0 = *(const uint4*)(pBlo + kn);  rd1 = *(const uint4*)(pBlo + kn + 8);
        }

        uint32_t base = sb + cur * GBUF;
#pragma unroll
        for (int ko = 0; ko < 32; ko += 16) {
            uint32_t fahi[4][4], fbhi[2][4], fblo[2][4];
#pragma unroll
            for (int mi = 0; mi < 4; mi++) {
                uint32_t off = ((aRow + mi * 16) * ASTR + ko + aColHalf) * 2;
                ldmat4(fahi[mi], base + 0 * GTILE + off);
            }
#pragma unroll
            for (int np = 0; np < 2; np++) {
                uint32_t off = ((bRow + np * 16) * ASTR + ko + bColHalf) * 2;
                ldmat4(fbhi[np], base + 1 * GTILE + off);
                ldmat4(fblo[np], base + 2 * GTILE + off);
            }
#pragma unroll
            for (int mi = 0; mi < 4; mi++) {
#pragma unroll
                for (int nt = 0; nt < 4; nt++) {
                    int np = nt >> 1, hf = (nt & 1) * 2;
                    uint32_t bh[2] = { fbhi[np][hf], fbhi[np][hf + 1] };
                    uint32_t bl[2] = { fblo[np][hf], fblo[np][hf + 1] };
                    mma16816(acc[mi][nt], fahi[mi], bh);
                    mma16816(acc[mi][nt], fahi[mi], bl);
                }
            }
        }

        if (more) {
            char* bn2 = gsm + (cur ^ 1u) * GBUF + stoff;
            *(uint4*)(bn2 + 0 * GTILE) = ra0; *(uint4*)(bn2 + 0 * GTILE + 16) = ra1;
            *(uint4*)(bn2 + 1 * GTILE) = rc0; *(uint4*)(bn2 + 1 * GTILE + 16) = rc1;
            *(uint4*)(bn2 + 2 * GTILE) = rd0; *(uint4*)(bn2 + 2 * GTILE + 16) = rd1;
        }
        __syncthreads();
        cur ^= 1u;
    }

#pragma unroll
    for (int nt = 0; nt < 4; nt++) {
        int col = bn + wn * 32 + nt * 8 + (lane & 3) * 2;
        float bv0 = 0.0f, bv1 = 0.0f;
        if (bias0) { bv0 += bias0[col]; bv1 += bias0[col + 1]; }
        if (bias1) { bv0 += bias1[col]; bv1 += bias1[col + 1]; }
#pragma unroll
        for (int mi = 0; mi < 4; mi++) {
            int row = bm + wm * 64 + mi * 16 + (lane >> 2);
            float2 v0 = make_float2(acc[mi][nt][0] + bv0, acc[mi][nt][1] + bv1);
            float2 v1 = make_float2(acc[mi][nt][2] + bv0, acc[mi][nt][3] + bv1);
            *(float2*)&C[(size_t)row * N + col] = v0;
            *(float2*)&C[(size_t)(row + 8) * N + col] = v1;
        }
    }
}

// =====================================================================
// Attention GEMM (2-term) + fused tanh-dot epilogue -> g_attn
// =====================================================================
__global__ void __launch_bounds__(256) gemm_att(const __nv_bfloat16* __restrict__ Ahi,
                                                const __nv_bfloat16* __restrict__ Bhi,
                                                const __nv_bfloat16* __restrict__ Blo,
                                                const float* __restrict__ bias0,
                                                const float* __restrict__ vatt,
                                                int M, int K) {
    __shared__ __nv_bfloat16 sAhi[128 * ASTR];
    __shared__ __nv_bfloat16 sBhi[128 * ASTR], sBlo[128 * ASTR];
    __shared__ float sred[128 * 4];

    int tid = threadIdx.x;
    int warp = tid >> 5, lane = tid & 31;
    int wm = warp >> 2, wn = warp & 3;
    int bm = blockIdx.y * 128;

    int lrow0 = tid >> 1;
    int lseg0 = (tid & 1) * 2;
    const __nv_bfloat16* pAhi = Ahi + (size_t)(bm + lrow0) * K + lseg0 * 8;
    const __nv_bfloat16* pBhi = Bhi + (size_t)lrow0 * K + lseg0 * 8;
    const __nv_bfloat16* pBlo = Blo + (size_t)lrow0 * K + lseg0 * 8;

    float acc[4][4][4];
#pragma unroll
    for (int i = 0; i < 4; i++)
#pragma unroll
        for (int j = 0; j < 4; j++)
#pragma unroll
            for (int q = 0; q < 4; q++) acc[i][j][q] = 0.0f;

    uint32_t aAhi = smem_u32(sAhi);
    uint32_t aBhi = smem_u32(sBhi), aBlo = smem_u32(sBlo);

    uint32_t aRow = (uint32_t)(wm * 64 + (lane & 15));
    uint32_t aColHalf = (uint32_t)((lane >> 4) * 8);
    uint32_t g = (uint32_t)(lane >> 3);
    uint32_t bRow = (uint32_t)(wn * 32 + ((g >> 1) * 8) + (lane & 7));
    uint32_t bColHalf = (g & 1) * 8;

    uint4 ra0, ra1, rc0, rc1, rd0, rd1;
    ra0 = *(const uint4*)pAhi;       ra1 = *(const uint4*)(pAhi + 8);
    rc0 = *(const uint4*)pBhi;       rc1 = *(const uint4*)(pBhi + 8);
    rd0 = *(const uint4*)pBlo;       rd1 = *(const uint4*)(pBlo + 8);

    int nchunks = K >> 5;
    for (int c0 = 0; c0 < nchunks; c0++) {
        {
            uint4* d;
            d = (uint4*)&sAhi[lrow0 * ASTR + lseg0 * 8]; d[0] = ra0; d[1] = ra1;
            d = (uint4*)&sBhi[lrow0 * ASTR + lseg0 * 8]; d[0] = rc0; d[1] = rc1;
            d = (uint4*)&sBlo[lrow0 * ASTR + lseg0 * 8]; d[0] = rd0; d[1] = rd1;
        }
        __syncthreads();

        if (c0 + 1 < nchunks) {
            int kn = (c0 + 1) << 5;
            ra0 = *(const uint4*)(pAhi + kn);  ra1 = *(const uint4*)(pAhi + kn + 8);
            rc0 = *(const uint4*)(pBhi + kn);  rc1 = *(const uint4*)(pBhi + kn + 8);
            rd0 = *(const uint4*)(pBlo + kn);  rd1 = *(const uint4*)(pBlo + kn + 8);
        }

#pragma unroll
        for (int ko = 0; ko < 32; ko += 16) {
            uint32_t fahi[4][4], fbhi[2][4], fblo[2][4];
#pragma unroll
            for (int mi = 0; mi < 4; mi++) {
                uint32_t off = ((aRow + mi * 16) * ASTR + ko + aColHalf) * 2;
                ldmat4(fahi[mi], aAhi + off);
            }
#pragma unroll
            for (int np = 0; np < 2; np++) {
                uint32_t off = ((bRow + np * 16) * ASTR + ko + bColHalf) * 2;
                ldmat4(fbhi[np], aBhi + off);
                ldmat4(fblo[np], aBlo + off);
            }
#pragma unroll
            for (int mi = 0; mi < 4; mi++) {
#pragma unroll
                for (int nt = 0; nt < 4; nt++) {
                    int np = nt >> 1, hf = (nt & 1) * 2;
                    uint32_t bh[2] = { fbhi[np][hf], fbhi[np][hf + 1] };
                    uint32_t bl[2] = { fblo[np][hf], fblo[np][hf + 1] };
                    mma16816(acc[mi][nt], fahi[mi], bh);
                    mma16816(acc[mi][nt], fahi[mi], bl);
                }
            }
        }
        __syncthreads();
    }

    float rsum[4][2];
#pragma unroll
    for (int mi = 0; mi < 4; mi++) { rsum[mi][0] = 0.0f; rsum[mi][1] = 0.0f; }
#pragma unroll
    for (int nt = 0; nt < 4; nt++) {
        int col = wn * 32 + nt * 8 + (lane & 3) * 2;
        float b0v = bias0[col], b1v = bias0[col + 1];
        float v0 = vatt[col], v1 = vatt[col + 1];
#pragma unroll
        for (int mi = 0; mi < 4; mi++) {
            rsum[mi][0] += ftanh(acc[mi][nt][0] + b0v) * v0
                         + ftanh(acc[mi][nt][1] + b1v) * v1;
            rsum[mi][1] += ftanh(acc[mi][nt][2] + b0v) * v0
                         + ftanh(acc[mi][nt][3] + b1v) * v1;
        }
    }
#pragma unroll
    for (int off = 1; off <= 2; off <<= 1) {
#pragma unroll
        for (int mi = 0; mi < 4; mi++) {
            rsum[mi][0] += __shfl_xor_sync(0xffffffffu, rsum[mi][0], off);
            rsum[mi][1] += __shfl_xor_sync(0xffffffffu, rsum[mi][1], off);
        }
    }
    if ((lane & 3) == 0) {
#pragma unroll
        for (int mi = 0; mi < 4; mi++) {
            int r0 = wm * 64 + mi * 16 + (lane >> 2);
            sred[r0 * 4 + wn] = rsum[mi][0];
            sred[(r0 + 8) * 4 + wn] = rsum[mi][1];
        }
    }
    __syncthreads();
    if (tid < 128) {
        g_attn[bm + tid] = sred[tid * 4] + sred[tid * 4 + 1] +
                           sred[tid * 4 + 2] + sred[tid * 4 + 3];
    }
}

// =====================================================================
// LSTM recurrence, 512 threads, FFMA2; epilogue writes bf16 hi only.
// =====================================================================
#define WPAD 132
#define REC_SMEM ((256 * WPAD + 512 + 512 + 4096) * 4)
__global__ void __launch_bounds__(512, 1) lstm_rec(const float* __restrict__ xp,
                                                   const float* __restrict__ Whh,
                                                   float* __restrict__ houtf,
                                                   __nv_bfloat16* __restrict__ hhi) {
    extern __shared__ float sm[];
    float* w_s = sm;
    float* h_s = w_s + 256 * WPAD;
    float* c_s = h_s + 512;
    float* gp  = c_s + 512;
    int tid = threadIdx.x;
    int t8 = tid & 255, kh = tid >> 8;
    int k0 = kh * 64;
    int b0 = blockIdx.x * 4;

    ulonglong2 w1r[16];
    const float* wg = Whh + (size_t)(256 + t8) * HH + k0;
#pragma unroll
    for (int i = 0; i < 16; i++) w1r[i] = __ldg((const ulonglong2*)(wg + 4 * i));

    for (int l = tid; l < 256 * HH; l += 512) {
        int r = l >> 7, k = l & 127;
        w_s[r * WPAD + k] = Whh[r * HH + k];
    }
    if (tid < 512) { h_s[tid] = 0.0f; c_s[tid] = 0.0f; }
    __syncthreads();

    const float* w0p = &w_s[t8 * WPAD + k0];

    int xrow = t8 + kh * 256;
    float xc[4];
    {
        const float* xpt = xp + (size_t)b0 * GG + xrow;
#pragma unroll
        for (int bb = 0; bb < 4; bb++) xc[bb] = xpt[bb * GG];
    }

    for (int t = 0; t < TT; t++) {
        unsigned long long a0v[4], a1v[4];
#pragma unroll
        for (int bb = 0; bb < 4; bb++) {
            a0v[bb] = packf2((kh == 0) ? xc[bb] : 0.0f, 0.0f);
            a1v[bb] = packf2((kh == 0) ? 0.0f : xc[bb], 0.0f);
        }

        if (t + 1 < TT) {
            const float* xn = xp + ((size_t)(t + 1) * BB + b0) * GG + xrow;
#pragma unroll
            for (int bb = 0; bb < 4; bb++) xc[bb] = xn[bb * GG];
        }

#pragma unroll
        for (int k4 = 0; k4 < 16; k4++) {
            ulonglong2 w0 = *(const ulonglong2*)(w0p + 4 * k4);
            ulonglong2 w1 = w1r[k4];
            int k = k0 + 4 * k4;
#pragma unroll
            for (int bb = 0; bb < 4; bb++) {
                ulonglong2 hb = *(const ulonglong2*)&h_s[bb * HH + k];
                ffma2(a0v[bb], hb.x, w0.x);
                ffma2(a0v[bb], hb.y, w0.y);
                ffma2(a1v[bb], hb.x, w1.x);
                ffma2(a1v[bb], hb.y, w1.y);
            }
        }
#pragma unroll
        for (int bb = 0; bb < 4; bb++) {
            float2 s0 = unpackf2(a0v[bb]);
            float2 s1 = unpackf2(a1v[bb]);
            gp[(kh * 4 + bb) * 512 + t8]       = s0.x + s0.y;
            gp[(kh * 4 + bb) * 512 + 256 + t8] = s1.x + s1.y;
        }
        __syncthreads();

        {
            int bb = tid >> 7, hh = tid & 127;
            const float* g0 = &gp[bb * 512];
            const float* g1 = &gp[(4 + bb) * 512];
            float gi = g0[hh]       + g1[hh];
            float gf = g0[128 + hh] + g1[128 + hh];
            float gc = g0[256 + hh] + g1[256 + hh];
            float go = g0[384 + hh] + g1[384 + hh];
            float cc = fsig(gf) * c_s[tid] + fsig(gi) * ftanh(gc);
            float h  = fsig(go) * ftanh(cc);
            c_s[tid] = cc;
            h_s[tid] = h;
            size_t oi = ((size_t)t * BB + b0 + bb) * HH + hh;
            hhi[oi] = __float2bfloat16(h);
            if (houtf) houtf[oi] = h;
        }
        __syncthreads();
    }
}

// ---------------- softmax + pool ----------------
__global__ void __launch_bounds__(128) pool_kernel() {
    int b = blockIdx.x;
    int tid = threadIdx.x;
    __shared__ float wt[TT];
    __shared__ float red[128];
    float a = (tid < TT) ? g_attn[tid * BB + b] : -1e30f;
    red[tid] = a;
    __syncthreads();
    for (int s = 64; s; s >>= 1) {
        if (tid < s) red[tid] = fmaxf(red[tid], red[tid + s]);
        __syncthreads();
    }
    float mx = red[0];
    __syncthreads();
    float e = (tid < TT) ? __expf(a - mx) : 0.0f;
    red[tid] = e;
    __syncthreads();
    for (int s = 64; s; s >>= 1) {
        if (tid < s) red[tid] += red[tid + s];
        __syncthreads();
    }
    float inv = __fdividef(1.0f, red[0]);
    if (tid < TT) wt[tid] = e * inv;
    __syncthreads();
    float acc = 0.0f;
#pragma unroll 4
    for (int t = 0; t < TT; t++)
        acc += wt[t] * g_h2[((size_t)t * BB + b) * HH + tid];
    g_pooled[b * HH + tid] = acc;
}

// ---------------- head ----------------
__global__ void __launch_bounds__(64) head_kernel(const float* __restrict__ W1,
                                                  const float* __restrict__ b1,
                                                  const float* __restrict__ W2,
                                                  const float* __restrict__ b2,
                                                  float* __restrict__ out) {
    int b = blockIdx.x;
    int tid = threadIdx.x;
    __shared__ float p[HH];
    __shared__ float hdn[64];
    for (int l = tid; l < HH; l += 64) p[l] = g_pooled[b * HH + l];
    __syncthreads();
    float acc = b1[tid];
#pragma unroll 8
    for (int k = 0; k < HH; k++) acc += p[k] * W1[tid * HH + k];
    hdn[tid] = acc;
    __syncthreads();
    if (tid < NC) {
        float o = b2[tid];
#pragma unroll
        for (int k = 0; k < 64; k++) o += hdn[k] * W2[tid * 64 + k];
        out[b * NC + tid] = o;
    }
}

// ---------------- host ----------------
extern "C" void kernel_launch(void* const* d_in, const int* in_sizes, int n_in,
                              void* d_out, int out_size) {
    const float* x      = (const float*)d_in[0];
    const float* conv_w = (const float*)d_in[1];
    const float* conv_b = (const float*)d_in[2];
    const float* Wih0   = (const float*)d_in[3];
    const float* Whh0   = (const float*)d_in[4];
    const float* bih0   = (const float*)d_in[5];
    const float* bhh0   = (const float*)d_in[6];
    const float* Wih1   = (const float*)d_in[7];
    const float* Whh1   = (const float*)d_in[8];
    const float* bih1   = (const float*)d_in[9];
    const float* bhh1   = (const float*)d_in[10];
    const float* W_att  = (const float*)d_in[11];
    const float* b_att  = (const float*)d_in[12];
    const float* v_att  = (const float*)d_in[13];
    const float* W1     = (const float*)d_in[14];
    const float* b1     = (const float*)d_in[15];
    const float* W2     = (const float*)d_in[16];
    const float* b2     = (const float*)d_in[17];
    float* out = (float*)d_out;

    float *xp_p, *h2_p;
    __nv_bfloat16 *Ahi_p, *W0hi_p, *W0lo_p, *W1hi_p, *W1lo_p, *Wahi_p, *Walo_p;
    cudaGetSymbolAddress((void**)&xp_p,    g_xp);
    cudaGetSymbolAddress((void**)&h2_p,    g_h2);
    cudaGetSymbolAddress((void**)&Ahi_p,  g_Ahi);
    cudaGetSymbolAddress((void**)&W0hi_p, g_W0hi);
    cudaGetSymbolAddress((void**)&W0lo_p, g_W0lo);
    cudaGetSymbolAddress((void**)&W1hi_p, g_W1hi);
    cudaGetSymbolAddress((void**)&W1lo_p, g_W1lo);
    cudaGetSymbolAddress((void**)&Wahi_p, g_Wahi);
    cudaGetSymbolAddress((void**)&Walo_p, g_Walo);

    cudaFuncSetAttribute(conv_kernel, cudaFuncAttributeMaxDynamicSharedMemorySize,
                         812 * 40 * 4);
    cudaFuncSetAttribute(lstm_rec, cudaFuncAttributeMaxDynamicSharedMemorySize,
                         REC_SMEM);
    cudaFuncSetAttribute(gemm_mma, cudaFuncAttributeMaxDynamicSharedMemorySize,
                         GSMEM);

    const int M = TT * BB;   // 51200

    // launches #1-#3: weight prep
    prep_a<<<(N4_W0 + 255) / 256, 256>>>(Wih0);
    prep_b<<<(N4_W1 + 255) / 256, 256>>>(Wih1);
    prep_c<<<(N4_WA + 255) / 256, 256>>>(W_att);

    // launch #4 (ncu capture slot): conv
    conv_kernel<<<BB, 256, 812 * 40 * 4>>>(x, conv_w, conv_b);

    gemm_mma<<<dim3(GG / 128, M / 128), 256, GSMEM>>>(Ahi_p, W0hi_p, W0lo_p,
                                                      bih0, bhh0, xp_p, M, GG, FF);
    lstm_rec<<<BB / 4, 512, REC_SMEM>>>(xp_p, Whh0, nullptr, Ahi_p);

    gemm_mma<<<dim3(GG / 128, M / 128), 256, GSMEM>>>(Ahi_p, W1hi_p, W1lo_p,
                                                      bih1, bhh1, xp_p, M, GG, HH);
    lstm_rec<<<BB / 4, 512, REC_SMEM>>>(xp_p, Whh1, h2_p, Ahi_p);

    gemm_att<<<dim3(1, M / 128), 256>>>(Ahi_p, Wahi_p, Walo_p,
                                        b_att, v_att, M, HH);
    pool_kernel<<<BB, 128>>>();
    head_kernel<<<BB, 64>>>(W1, b1, W2, b2, out);
}